// round 5
// baseline (speedup 1.0000x reference)
#include <cuda_runtime.h>
#include <cstdint>

#define L_  2048
#define S_  2048
#define B_  4
#define E_  1024
#define H_  16
#define HD_ 64
#define FF_ 4096
#define M_  (L_*B_)      /* 8192 rows (l*B+b) */
#define EPS_ 1e-5f

// ---------------- device scratch (no allocations allowed) ----------------
__device__ float g_q [M_*E_];
__device__ float g_k [M_*E_];
__device__ float g_v [M_*E_];
__device__ float g_ao[M_*E_];
__device__ float g_t [M_*E_];
__device__ float g_x1[M_*E_];
__device__ float g_x2[M_*E_];
__device__ float g_x1r[M_*E_];
__device__ float g_x2r[M_*E_];
__device__ float g_tr[M_*E_];
__device__ float g_mr[M_*E_];
__device__ float g_h [M_*FF_];
__device__ float g_wt[8*E_*E_ + 2*E_*FF_];

// ---------------- small PTX helpers --------------------------------------
__device__ __forceinline__ uint32_t f2tf(float x) {
    uint32_t r;
    asm("cvt.rna.tf32.f32 %0, %1;" : "=r"(r) : "f"(x));
    return r;
}
__device__ __forceinline__ void cpa16(void* smem, const void* gmem) {
    uint32_t s = (uint32_t)__cvta_generic_to_shared(smem);
    asm volatile("cp.async.cg.shared.global [%0], [%1], 16;" :: "r"(s), "l"(gmem));
}
__device__ __forceinline__ void mma_tf32(float* d, const uint32_t* a, const uint32_t* b) {
    asm volatile(
        "mma.sync.aligned.m16n8k8.row.col.f32.tf32.tf32.f32 "
        "{%0,%1,%2,%3}, {%4,%5,%6,%7}, {%8,%9}, {%0,%1,%2,%3};"
        : "+f"(d[0]), "+f"(d[1]), "+f"(d[2]), "+f"(d[3])
        : "r"(a[0]), "r"(a[1]), "r"(a[2]), "r"(a[3]), "r"(b[0]), "r"(b[1]));
}

// ---------------- elementwise tf32 round ----------------------------------
__global__ void round_tf32_kernel(const float* __restrict__ in,
                                  float* __restrict__ out, int n4) {
    int i = blockIdx.x * blockDim.x + threadIdx.x;
    if (i < n4) {
        float4 v = *(const float4*)&in[i * 4];
        v.x = __uint_as_float(f2tf(v.x));
        v.y = __uint_as_float(f2tf(v.y));
        v.z = __uint_as_float(f2tf(v.z));
        v.w = __uint_as_float(f2tf(v.w));
        *(float4*)&out[i * 4] = v;
    }
}

// ---------------- TF32 tensor-core GEMM -----------------------------------
// C[M,N] = A[M,K] @ W^T + bias, W given [N,K] (native layout, pre-rounded).
// A pre-rounded to tf32 in gmem -> ALL fragment loads are raw bits, no cvt.
// 128x256 block tile, BK=16, 8 warps (2x4), warp tile 64x64, 4-stage cp.async.
#define GBM 128
#define GBN 256
#define GBK 16
#define GPAD 20
#define NSTG 4
#define GEMM_SMEM (NSTG*(GBM + GBN)*GPAD*4)   /* 122880 bytes */

template <bool RELU, bool ROUND>
__global__ __launch_bounds__(256, 1)
void gemm_tf32_kernel(const float* __restrict__ A, const float* __restrict__ W,
                      const float* __restrict__ bias, float* __restrict__ C,
                      int M, int N, int K) {
    extern __shared__ float sm[];
    float (*As)[GBM][GPAD] = (float (*)[GBM][GPAD])sm;
    float (*Bs)[GBN][GPAD] = (float (*)[GBN][GPAD])(sm + NSTG * GBM * GPAD);

    const int tid  = threadIdx.x;
    const int lane = tid & 31, warp = tid >> 5;
    const int gid  = lane >> 2, tig = lane & 3;
    const int wm   = (warp & 1) * 64;
    const int wn   = (warp >> 1) * 64;
    const int m0   = blockIdx.y * GBM, n0 = blockIdx.x * GBN;

    const int arow = tid >> 2, ak4 = (tid & 3) * 4;    // A: 128 rows x 16 k

    float acc[4][8][4];
    #pragma unroll
    for (int mt = 0; mt < 4; mt++)
        #pragma unroll
        for (int nt = 0; nt < 8; nt++)
            #pragma unroll
            for (int i = 0; i < 4; i++) acc[mt][nt][i] = 0.0f;

    const int nK = K / GBK;

    #define LOAD_STAGE(s, k0)                                                        \
        do {                                                                         \
            cpa16(&As[s][arow][ak4],      &A[(size_t)(m0 + arow) * K + (k0) + ak4]); \
            cpa16(&As[s][arow + 64][ak4], &A[(size_t)(m0 + arow + 64) * K + (k0) + ak4]); \
            _Pragma("unroll")                                                        \
            for (int j = 0; j < 4; j++)                                              \
                cpa16(&Bs[s][tid][j * 4],                                            \
                      &W[(size_t)(n0 + tid) * K + (k0) + j * 4]);                    \
            asm volatile("cp.async.commit_group;");                                  \
        } while (0)

    LOAD_STAGE(0, 0);
    LOAD_STAGE(1, GBK);
    LOAD_STAGE(2, 2 * GBK);

    for (int kt = 0; kt < nK; kt++) {
        asm volatile("cp.async.wait_group 2;");
        __syncthreads();
        const int st = kt & 3;
        if (kt + 3 < nK) {
            LOAD_STAGE((kt + 3) & 3, (kt + 3) * GBK);
        }
        #pragma unroll
        for (int kk = 0; kk < GBK; kk += 8) {
            uint32_t af[4][4], bf[8][2];
            #pragma unroll
            for (int mt = 0; mt < 4; mt++) {
                int mr = wm + mt * 16 + gid;
                af[mt][0] = __float_as_uint(As[st][mr    ][kk + tig]);
                af[mt][1] = __float_as_uint(As[st][mr + 8][kk + tig]);
                af[mt][2] = __float_as_uint(As[st][mr    ][kk + tig + 4]);
                af[mt][3] = __float_as_uint(As[st][mr + 8][kk + tig + 4]);
            }
            #pragma unroll
            for (int nt = 0; nt < 8; nt++) {
                int nc = wn + nt * 8 + gid;
                bf[nt][0] = __float_as_uint(Bs[st][nc][kk + tig]);
                bf[nt][1] = __float_as_uint(Bs[st][nc][kk + tig + 4]);
            }
            #pragma unroll
            for (int mt = 0; mt < 4; mt++)
                #pragma unroll
                for (int nt = 0; nt < 8; nt++)
                    mma_tf32(acc[mt][nt], af[mt], bf[nt]);
        }
        __syncthreads();
    }
    #undef LOAD_STAGE

    #pragma unroll
    for (int mt = 0; mt < 4; mt++) {
        int r0 = m0 + wm + mt * 16 + gid;
        #pragma unroll
        for (int nt = 0; nt < 8; nt++) {
            int col = n0 + wn + nt * 8 + tig * 2;
            float bb0 = bias[col], bb1 = bias[col + 1];
            float v0 = acc[mt][nt][0] + bb0, v1 = acc[mt][nt][1] + bb1;
            float v2 = acc[mt][nt][2] + bb0, v3 = acc[mt][nt][3] + bb1;
            if (RELU) {
                v0 = fmaxf(v0, 0.f); v1 = fmaxf(v1, 0.f);
                v2 = fmaxf(v2, 0.f); v3 = fmaxf(v3, 0.f);
            }
            if (ROUND) {
                v0 = __uint_as_float(f2tf(v0)); v1 = __uint_as_float(f2tf(v1));
                v2 = __uint_as_float(f2tf(v2)); v3 = __uint_as_float(f2tf(v3));
            }
            *(float2*)&C[(size_t)r0 * N + col]       = make_float2(v0, v1);
            *(float2*)&C[(size_t)(r0 + 8) * N + col] = make_float2(v2, v3);
        }
    }
}

// ---------------- flash attention on tensor cores (TF32, HD=64) ------------
#define FL_SMEM (2*64*68*4 + 2*64*72*4)   /* 71680 bytes */

template <bool CAUSAL>
__global__ __launch_bounds__(256)
void flash_mma_kernel(const float* __restrict__ Q, const float* __restrict__ Kg,
                      const float* __restrict__ Vg, float* __restrict__ O, int Slen) {
    extern __shared__ float fsm[];
    float (*Ks)[64][68] = (float (*)[64][68])fsm;
    float (*Vs)[64][72] = (float (*)[64][72])(fsm + 2 * 64 * 68);

    const int tid = threadIdx.x, warp = tid >> 5, lane = tid & 31;
    const int gid = lane >> 2, tig = lane & 3;
    const int bh = blockIdx.y, b = bh >> 4, h = bh & 15;
    const int l0 = blockIdx.x * 128;
    const int col = h * HD_;
    const int rw = l0 + warp * 16;

    uint32_t qf[8][4];
    {
        const float* q0 = &Q[((size_t)(rw + gid) * B_ + b) * E_ + col];
        const float* q1 = &Q[((size_t)(rw + gid + 8) * B_ + b) * E_ + col];
        #pragma unroll
        for (int kk = 0; kk < 8; kk++) {
            qf[kk][0] = __float_as_uint(q0[kk * 8 + tig] * 0.125f);
            qf[kk][1] = __float_as_uint(q1[kk * 8 + tig] * 0.125f);
            qf[kk][2] = __float_as_uint(q0[kk * 8 + tig + 4] * 0.125f);
            qf[kk][3] = __float_as_uint(q1[kk * 8 + tig + 4] * 0.125f);
        }
    }

    float of[8][4];
    #pragma unroll
    for (int nt = 0; nt < 8; nt++)
        of[nt][0] = of[nt][1] = of[nt][2] = of[nt][3] = 0.f;
    float m0 = -1e30f, m1 = -1e30f, la0 = 0.f, la1 = 0.f;

    const int T = CAUSAL ? (l0 / 64 + 2) : (Slen / 64);

    {
        #pragma unroll
        for (int i = 0; i < 4; i++) {
            int idx = tid + i * 256;
            int r = idx >> 4, c4 = (idx & 15) * 4;
            size_t goff = ((size_t)r * B_ + b) * E_ + col + c4;
            cpa16(&Ks[0][r][c4], &Kg[goff]);
            cpa16(&Vs[0][r][c4], &Vg[goff]);
        }
        asm volatile("cp.async.commit_group;");
    }

    for (int t = 0; t < T; t++) {
        const int bf = t & 1;
        if (t + 1 < T) {
            const int s1 = (t + 1) * 64, b2 = bf ^ 1;
            #pragma unroll
            for (int i = 0; i < 4; i++) {
                int idx = tid + i * 256;
                int r = idx >> 4, c4 = (idx & 15) * 4;
                size_t goff = ((size_t)(s1 + r) * B_ + b) * E_ + col + c4;
                cpa16(&Ks[b2][r][c4], &Kg[goff]);
                cpa16(&Vs[b2][r][c4], &Vg[goff]);
            }
            asm volatile("cp.async.commit_group;");
            asm volatile("cp.async.wait_group 1;");
        } else {
            asm volatile("cp.async.wait_group 0;");
        }
        __syncthreads();

        const int s0 = t * 64;
        if (!CAUSAL || s0 <= rw) {
            float sf[8][4];
            #pragma unroll
            for (int nt = 0; nt < 8; nt++)
                sf[nt][0] = sf[nt][1] = sf[nt][2] = sf[nt][3] = 0.f;
            #pragma unroll
            for (int kk = 0; kk < 8; kk++) {
                #pragma unroll
                for (int nt = 0; nt < 8; nt++) {
                    uint32_t bb[2];
                    bb[0] = __float_as_uint(Ks[bf][nt * 8 + gid][kk * 8 + tig]);
                    bb[1] = __float_as_uint(Ks[bf][nt * 8 + gid][kk * 8 + tig + 4]);
                    mma_tf32(sf[nt], qf[kk], bb);
                }
            }
            if (CAUSAL && s0 + 63 > rw) {
                int r0 = rw + gid, r1 = r0 + 8;
                #pragma unroll
                for (int nt = 0; nt < 8; nt++) {
                    int c = s0 + nt * 8 + 2 * tig;
                    if (c     > r0) sf[nt][0] = -1e30f;
                    if (c + 1 > r0) sf[nt][1] = -1e30f;
                    if (c     > r1) sf[nt][2] = -1e30f;
                    if (c + 1 > r1) sf[nt][3] = -1e30f;
                }
            }
            float mx0 = -1e30f, mx1 = -1e30f;
            #pragma unroll
            for (int nt = 0; nt < 8; nt++) {
                mx0 = fmaxf(mx0, fmaxf(sf[nt][0], sf[nt][1]));
                mx1 = fmaxf(mx1, fmaxf(sf[nt][2], sf[nt][3]));
            }
            mx0 = fmaxf(mx0, __shfl_xor_sync(0xffffffffu, mx0, 1));
            mx0 = fmaxf(mx0, __shfl_xor_sync(0xffffffffu, mx0, 2));
            mx1 = fmaxf(mx1, __shfl_xor_sync(0xffffffffu, mx1, 1));
            mx1 = fmaxf(mx1, __shfl_xor_sync(0xffffffffu, mx1, 2));
            float mn0 = fmaxf(m0, mx0), mn1 = fmaxf(m1, mx1);
            float f0 = __expf(m0 - mn0), f1 = __expf(m1 - mn1);
            m0 = mn0;  m1 = mn1;
            float ss0 = 0.f, ss1 = 0.f;
            #pragma unroll
            for (int nt = 0; nt < 8; nt++) {
                sf[nt][0] = __expf(sf[nt][0] - m0);  ss0 += sf[nt][0];
                sf[nt][1] = __expf(sf[nt][1] - m0);  ss0 += sf[nt][1];
                sf[nt][2] = __expf(sf[nt][2] - m1);  ss1 += sf[nt][2];
                sf[nt][3] = __expf(sf[nt][3] - m1);  ss1 += sf[nt][3];
            }
            ss0 += __shfl_xor_sync(0xffffffffu, ss0, 1);
            ss0 += __shfl_xor_sync(0xffffffffu, ss0, 2);
            ss1 += __shfl_xor_sync(0xffffffffu, ss1, 1);
            ss1 += __shfl_xor_sync(0xffffffffu, ss1, 2);
            la0 = la0 * f0 + ss0;
            la1 = la1 * f1 + ss1;
            #pragma unroll
            for (int nt = 0; nt < 8; nt++) {
                of[nt][0] *= f0;  of[nt][1] *= f0;
                of[nt][2] *= f1;  of[nt][3] *= f1;
            }
            const int src0 = (lane & ~3) | (tig >> 1);
            const bool odd = (tig & 1) != 0;
            #pragma unroll
            for (int kk = 0; kk < 8; kk++) {
                float v0 = __shfl_sync(0xffffffffu, sf[kk][0], src0);
                float v1 = __shfl_sync(0xffffffffu, sf[kk][1], src0);
                float v2 = __shfl_sync(0xffffffffu, sf[kk][2], src0);
                float v3 = __shfl_sync(0xffffffffu, sf[kk][3], src0);
                float w0 = __shfl_sync(0xffffffffu, sf[kk][0], src0 + 2);
                float w1 = __shfl_sync(0xffffffffu, sf[kk][1], src0 + 2);
                float w2 = __shfl_sync(0xffffffffu, sf[kk][2], src0 + 2);
                float w3 = __shfl_sync(0xffffffffu, sf[kk][3], src0 + 2);
                uint32_t a[4];
                a[0] = f2tf(odd ? v1 : v0);
                a[1] = f2tf(odd ? v3 : v2);
                a[2] = f2tf(odd ? w1 : w0);
                a[3] = f2tf(odd ? w3 : w2);
                #pragma unroll
                for (int nt = 0; nt < 8; nt++) {
                    uint32_t bb[2];
                    bb[0] = __float_as_uint(Vs[bf][kk * 8 + tig][nt * 8 + gid]);
                    bb[1] = __float_as_uint(Vs[bf][kk * 8 + tig + 4][nt * 8 + gid]);
                    mma_tf32(of[nt], a, bb);
                }
            }
        }
        __syncthreads();
    }

    // output rounded to tf32 so the out-projection GEMM can raw-load it
    const float inv0 = 1.f / la0, inv1 = 1.f / la1;
    const int r0 = rw + gid, r1 = r0 + 8;
    #pragma unroll
    for (int nt = 0; nt < 8; nt++) {
        int c = col + nt * 8 + 2 * tig;
        *(float2*)&O[((size_t)r0 * B_ + b) * E_ + c] =
            make_float2(__uint_as_float(f2tf(of[nt][0] * inv0)),
                        __uint_as_float(f2tf(of[nt][1] * inv0)));
        *(float2*)&O[((size_t)r1 * B_ + b) * E_ + c] =
            make_float2(__uint_as_float(f2tf(of[nt][2] * inv1)),
                        __uint_as_float(f2tf(of[nt][3] * inv1)));
    }
}

// ---------------- fused residual + LayerNorm (+opt rounded twin) -----------
template <bool WR>
__global__ __launch_bounds__(256)
void add_ln_kernel(const float* __restrict__ A, const float* __restrict__ Bb,
                   const float* __restrict__ g, const float* __restrict__ be,
                   float* __restrict__ out, float* __restrict__ outR) {
    __shared__ float rbuf[8];
    __shared__ float stat;
    int row = blockIdx.x, tid = threadIdx.x, lane = tid & 31, warp = tid >> 5;
    size_t base = (size_t)row * E_ + tid * 4;

    float4 a = *(const float4*)&A[base];
    float4 b = *(const float4*)&Bb[base];
    float4 x = make_float4(a.x + b.x, a.y + b.y, a.z + b.z, a.w + b.w);

    float s = x.x + x.y + x.z + x.w;
    #pragma unroll
    for (int off = 16; off > 0; off >>= 1) s += __shfl_xor_sync(0xffffffffu, s, off);
    if (lane == 0) rbuf[warp] = s;
    __syncthreads();
    if (tid == 0) {
        float t = 0.f;
        #pragma unroll
        for (int i = 0; i < 8; i++) t += rbuf[i];
        stat = t * (1.0f / E_);
    }
    __syncthreads();
    float mu = stat;

    float4 dx = make_float4(x.x - mu, x.y - mu, x.z - mu, x.w - mu);
    float sq = dx.x * dx.x + dx.y * dx.y + dx.z * dx.z + dx.w * dx.w;
    #pragma unroll
    for (int off = 16; off > 0; off >>= 1) sq += __shfl_xor_sync(0xffffffffu, sq, off);
    if (lane == 0) rbuf[warp] = sq;
    __syncthreads();
    if (tid == 0) {
        float t = 0.f;
        #pragma unroll
        for (int i = 0; i < 8; i++) t += rbuf[i];
        stat = rsqrtf(t * (1.0f / E_) + EPS_);
    }
    __syncthreads();
    float rs = stat;

    float4 gv = *(const float4*)&g[tid * 4];
    float4 bv = *(const float4*)&be[tid * 4];
    float4 y = make_float4(dx.x * rs * gv.x + bv.x, dx.y * rs * gv.y + bv.y,
                           dx.z * rs * gv.z + bv.z, dx.w * rs * gv.w + bv.w);
    *(float4*)&out[base] = y;
    if (WR) {
        float4 yr = make_float4(__uint_as_float(f2tf(y.x)), __uint_as_float(f2tf(y.y)),
                                __uint_as_float(f2tf(y.z)), __uint_as_float(f2tf(y.w)));
        *(float4*)&outR[base] = yr;
    }
}

// ---------------- launcher ------------------------------------------------
extern "C" void kernel_launch(void* const* d_in, const int* in_sizes, int n_in,
                              void* d_out, int out_size) {
    (void)in_sizes; (void)n_in; (void)out_size;
    const float* tgt  = (const float*)d_in[0];
    const float* memi = (const float*)d_in[1];
    // d_in[2] = tgt_mask: strictly causal by construction; causal predicate used instead.
    const float* saWq = (const float*)d_in[3];  const float* sabq = (const float*)d_in[4];
    const float* saWk = (const float*)d_in[5];  const float* sabk = (const float*)d_in[6];
    const float* saWv = (const float*)d_in[7];  const float* sabv = (const float*)d_in[8];
    const float* saWo = (const float*)d_in[9];  const float* sabo = (const float*)d_in[10];
    const float* caWq = (const float*)d_in[11]; const float* cabq = (const float*)d_in[12];
    const float* caWk = (const float*)d_in[13]; const float* cabk = (const float*)d_in[14];
    const float* caWv = (const float*)d_in[15]; const float* cabv = (const float*)d_in[16];
    const float* caWo = (const float*)d_in[17]; const float* cabo = (const float*)d_in[18];
    const float* W1   = (const float*)d_in[19]; const float* b1   = (const float*)d_in[20];
    const float* W2   = (const float*)d_in[21]; const float* b2   = (const float*)d_in[22];
    const float* ln1g = (const float*)d_in[23]; const float* ln1b = (const float*)d_in[24];
    const float* ln2g = (const float*)d_in[25]; const float* ln2b = (const float*)d_in[26];
    const float* ln3g = (const float*)d_in[27]; const float* ln3b = (const float*)d_in[28];

    float *q, *k, *v, *ao, *t, *x1, *x2, *x1r, *x2r, *tr, *mr, *hh, *wt;
    cudaGetSymbolAddress((void**)&q,   g_q);
    cudaGetSymbolAddress((void**)&k,   g_k);
    cudaGetSymbolAddress((void**)&v,   g_v);
    cudaGetSymbolAddress((void**)&ao,  g_ao);
    cudaGetSymbolAddress((void**)&t,   g_t);
    cudaGetSymbolAddress((void**)&x1,  g_x1);
    cudaGetSymbolAddress((void**)&x2,  g_x2);
    cudaGetSymbolAddress((void**)&x1r, g_x1r);
    cudaGetSymbolAddress((void**)&x2r, g_x2r);
    cudaGetSymbolAddress((void**)&tr,  g_tr);
    cudaGetSymbolAddress((void**)&mr,  g_mr);
    cudaGetSymbolAddress((void**)&hh,  g_h);
    cudaGetSymbolAddress((void**)&wt,  g_wt);

    cudaFuncSetAttribute(flash_mma_kernel<true>,
                         cudaFuncAttributeMaxDynamicSharedMemorySize, FL_SMEM);
    cudaFuncSetAttribute(flash_mma_kernel<false>,
                         cudaFuncAttributeMaxDynamicSharedMemorySize, FL_SMEM);
    cudaFuncSetAttribute(gemm_tf32_kernel<false, true>,
                         cudaFuncAttributeMaxDynamicSharedMemorySize, GEMM_SMEM);
    cudaFuncSetAttribute(gemm_tf32_kernel<false, false>,
                         cudaFuncAttributeMaxDynamicSharedMemorySize, GEMM_SMEM);
    cudaFuncSetAttribute(gemm_tf32_kernel<true, true>,
                         cudaFuncAttributeMaxDynamicSharedMemorySize, GEMM_SMEM);

    // rounded weights, native [N,K] layout
    float* wsaq = wt + 0 * E_ * E_;
    float* wsak = wt + 1 * E_ * E_;
    float* wsav = wt + 2 * E_ * E_;
    float* wsao = wt + 3 * E_ * E_;
    float* wcaq = wt + 4 * E_ * E_;
    float* wcak = wt + 5 * E_ * E_;
    float* wcav = wt + 6 * E_ * E_;
    float* wcao = wt + 7 * E_ * E_;
    float* ww1  = wt + 8 * E_ * E_;
    float* ww2  = wt + 8 * E_ * E_ + E_ * FF_;

    const int RT = 256;
    const int nEE   = E_ * E_ / 4;     // 262144
    const int nEFF  = E_ * FF_ / 4;    // 1048576
    const int nME   = M_ * E_ / 4;     // 2097152
    dim3 g1(E_ / GBN, M_ / GBM);       // (4, 64)
    dim3 gf(FF_ / GBN, M_ / GBM);      // (16, 64)
    dim3 ga(L_ / 128, B_ * H_);        // (16, 64)

    // ---- self attention block ----
    round_tf32_kernel<<<(nME + RT - 1) / RT, RT>>>(tgt,  tr,   nME);   // #0
    round_tf32_kernel<<<(nEE + RT - 1) / RT, RT>>>(saWq, wsaq, nEE);   // #1
    round_tf32_kernel<<<(nEE + RT - 1) / RT, RT>>>(saWk, wsak, nEE);   // #2
    round_tf32_kernel<<<(nEE + RT - 1) / RT, RT>>>(saWv, wsav, nEE);   // #3
    gemm_tf32_kernel<false, true ><<<g1, 256, GEMM_SMEM>>>(tr, wsaq, sabq, q, M_, E_, E_); // #4
    gemm_tf32_kernel<false, true ><<<g1, 256, GEMM_SMEM>>>(tr, wsak, sabk, k, M_, E_, E_); // #5
    gemm_tf32_kernel<false, true ><<<g1, 256, GEMM_SMEM>>>(tr, wsav, sabv, v, M_, E_, E_);
    round_tf32_kernel<<<(nEE + RT - 1) / RT, RT>>>(saWo, wsao, nEE);
    flash_mma_kernel<true><<<ga, 256, FL_SMEM>>>(q, k, v, ao, L_);
    gemm_tf32_kernel<false, false><<<g1, 256, GEMM_SMEM>>>(ao, wsao, sabo, t, M_, E_, E_);
    add_ln_kernel<true><<<M_, 256>>>(tgt, t, ln1g, ln1b, x1, x1r);

    // ---- cross attention block ----
    round_tf32_kernel<<<(nME + RT - 1) / RT, RT>>>(memi, mr,   nME);
    round_tf32_kernel<<<(nEE + RT - 1) / RT, RT>>>(caWq, wcaq, nEE);
    round_tf32_kernel<<<(nEE + RT - 1) / RT, RT>>>(caWk, wcak, nEE);
    round_tf32_kernel<<<(nEE + RT - 1) / RT, RT>>>(caWv, wcav, nEE);
    round_tf32_kernel<<<(nEE + RT - 1) / RT, RT>>>(caWo, wcao, nEE);
    gemm_tf32_kernel<false, true ><<<g1, 256, GEMM_SMEM>>>(x1r, wcaq, cabq, q, M_, E_, E_);
    gemm_tf32_kernel<false, true ><<<g1, 256, GEMM_SMEM>>>(mr,  wcak, cabk, k, M_, E_, E_);
    gemm_tf32_kernel<false, true ><<<g1, 256, GEMM_SMEM>>>(mr,  wcav, cabv, v, M_, E_, E_);
    flash_mma_kernel<false><<<ga, 256, FL_SMEM>>>(q, k, v, ao, S_);
    gemm_tf32_kernel<false, false><<<g1, 256, GEMM_SMEM>>>(ao, wcao, cabo, t, M_, E_, E_);
    add_ln_kernel<true><<<M_, 256>>>(x1, t, ln2g, ln2b, x2, x2r);

    // ---- FFN block ----
    round_tf32_kernel<<<(nEFF + RT - 1) / RT, RT>>>(W1, ww1, nEFF);
    round_tf32_kernel<<<(nEFF + RT - 1) / RT, RT>>>(W2, ww2, nEFF);
    gemm_tf32_kernel<true,  true ><<<gf, 256, GEMM_SMEM>>>(x2r, ww1, b1, hh, M_, FF_, E_);
    gemm_tf32_kernel<false, false><<<g1, 256, GEMM_SMEM>>>(hh,  ww2, b2, t,  M_, E_, FF_);
    add_ln_kernel<false><<<M_, 256>>>(x2, t, ln3g, ln3b, (float*)d_out, nullptr);
}

// round 6
// speedup vs baseline: 1.0441x; 1.0441x over previous
#include <cuda_runtime.h>
#include <cstdint>

#define L_  2048
#define S_  2048
#define B_  4
#define E_  1024
#define H_  16
#define HD_ 64
#define FF_ 4096
#define M_  (L_*B_)      /* 8192 rows (l*B+b) */
#define EPS_ 1e-5f

// ---------------- device scratch (no allocations allowed) ----------------
__device__ float g_qkv[M_*3*E_];
__device__ float g_q  [M_*E_];
__device__ float g_kv [M_*2*E_];
__device__ float g_ao [M_*E_];
__device__ float g_t  [M_*E_];
__device__ float g_x1 [M_*E_];
__device__ float g_x2 [M_*E_];
__device__ float g_x1r[M_*E_];
__device__ float g_x2r[M_*E_];
__device__ float g_tr [M_*E_];
__device__ float g_mr [M_*E_];
__device__ float g_h  [M_*FF_];
__device__ float g_wt [8*E_*E_ + 2*E_*FF_];   /* 16M floats, exactly used */

// ---------------- small PTX helpers --------------------------------------
__device__ __forceinline__ uint32_t f2tf(float x) {
    uint32_t r;
    asm("cvt.rna.tf32.f32 %0, %1;" : "=r"(r) : "f"(x));
    return r;
}
__device__ __forceinline__ void cpa16(void* smem, const void* gmem) {
    uint32_t s = (uint32_t)__cvta_generic_to_shared(smem);
    asm volatile("cp.async.cg.shared.global [%0], [%1], 16;" :: "r"(s), "l"(gmem));
}
__device__ __forceinline__ void mma_tf32(float* d, const uint32_t* a, const uint32_t* b) {
    asm volatile(
        "mma.sync.aligned.m16n8k8.row.col.f32.tf32.tf32.f32 "
        "{%0,%1,%2,%3}, {%4,%5,%6,%7}, {%8,%9}, {%0,%1,%2,%3};"
        : "+f"(d[0]), "+f"(d[1]), "+f"(d[2]), "+f"(d[3])
        : "r"(a[0]), "r"(a[1]), "r"(a[2]), "r"(a[3]), "r"(b[0]), "r"(b[1]));
}
#define LDSM4(r, addr)                                                        \
    asm volatile("ldmatrix.sync.aligned.m8n8.x4.shared.b16 {%0,%1,%2,%3}, [%4];" \
                 : "=r"((r)[0]), "=r"((r)[1]), "=r"((r)[2]), "=r"((r)[3])      \
                 : "r"(addr))

// ---------------- elementwise tf32 round ----------------------------------
__global__ void round_tf32_kernel(const float* __restrict__ in,
                                  float* __restrict__ out, int n4) {
    int i = blockIdx.x * blockDim.x + threadIdx.x;
    if (i < n4) {
        float4 v = *(const float4*)&in[i * 4];
        v.x = __uint_as_float(f2tf(v.x));
        v.y = __uint_as_float(f2tf(v.y));
        v.z = __uint_as_float(f2tf(v.z));
        v.w = __uint_as_float(f2tf(v.w));
        *(float4*)&out[i * 4] = v;
    }
}

// ---------------- weight pack: W[Nsrc,K] -> blocked [(k/16)][Ntot n][16 k]
// dst word index = ((k>>4)*Ntot + n_off + n)*16 + (k&15); rounded to tf32.
__global__ void pack_w_kernel(const float* __restrict__ src, float* __restrict__ dst,
                              int n_off, int Ntot, int Nsrc, int K) {
    int i = blockIdx.x * blockDim.x + threadIdx.x;
    int total4 = Nsrc * K / 4;
    if (i < total4) {
        int e = i * 4;
        int n = e / K, k = e % K;
        float4 v = *(const float4*)&src[e];
        v.x = __uint_as_float(f2tf(v.x));
        v.y = __uint_as_float(f2tf(v.y));
        v.z = __uint_as_float(f2tf(v.z));
        v.w = __uint_as_float(f2tf(v.w));
        size_t o = ((size_t)(k >> 4) * Ntot + n_off + n) * 16 + (k & 15);
        *(float4*)&dst[o] = v;
    }
}

// ---------------- TF32 tensor-core GEMM (ldmatrix, cvt-free) ---------------
// C[M,N] = A[M,K] @ W^T + bias. A pre-rounded tf32 row-major; W pre-packed
// blocked. 128x256 block tile, BK=16, 8 warps (2x4), warp tile 64x64,
// 4-stage cp.async, fragments via ldmatrix.x4 (A: [m][k] pad20; B: [n][k] pad20).
#define GBM 128
#define GBN 256
#define GBK 16
#define APAD 20
#define ASTG (GBM*APAD)          /* words per A stage = 2560 */
#define BSTG (GBN*APAD)          /* words per B stage = 5120 */
#define NSTG 4
#define GEMM_SMEM (NSTG*(ASTG+BSTG)*4)   /* 122880 bytes */

template <bool RELU, bool ROUND, int NBSEL>
__global__ __launch_bounds__(256, 1)
void gemm_tf32_kernel(const float* __restrict__ A, const float* __restrict__ W,
                      const float* __restrict__ b0p, const float* __restrict__ b1p,
                      const float* __restrict__ b2p, float* __restrict__ C,
                      int M, int N, int K) {
    extern __shared__ float sm[];

    const int tid  = threadIdx.x;
    const int lane = tid & 31, warp = tid >> 5;
    const int gid  = lane >> 2, tig = lane & 3;
    const int wm   = (warp & 1) * 64;
    const int wn   = (warp >> 1) * 64;
    const int m0   = blockIdx.y * GBM, n0 = blockIdx.x * GBN;

    const int arow = tid >> 2, ak4 = (tid & 3) * 4;    // A: 128 rows x 16 k

    const uint32_t smb = (uint32_t)__cvta_generic_to_shared(sm);
    // per-lane ldmatrix base addresses (stage 0, kk = 0), bytes
    uint32_t aAddr[4], bAddr[4];
    #pragma unroll
    for (int mt = 0; mt < 4; mt++)
        aAddr[mt] = smb + (((wm + mt * 16 + (lane & 15)) * APAD + ((lane >> 4) << 2)) << 2);
    #pragma unroll
    for (int p = 0; p < 4; p++)
        bAddr[p] = smb + ((NSTG * ASTG +
                   (wn + p * 16 + (lane & 7) + ((lane >> 4) << 3)) * APAD +
                   (((lane >> 3) & 1) << 2)) << 2);

    float acc[4][8][4];
    #pragma unroll
    for (int mt = 0; mt < 4; mt++)
        #pragma unroll
        for (int nt = 0; nt < 8; nt++)
            #pragma unroll
            for (int i = 0; i < 4; i++) acc[mt][nt][i] = 0.0f;

    const int nK = K / GBK;

    #define LOAD_STAGE(s, k0)                                                          \
        do {                                                                           \
            float* As_ = sm + (s) * ASTG;                                              \
            float* Bs_ = sm + NSTG * ASTG + (s) * BSTG;                                \
            cpa16(&As_[arow * APAD + ak4],        &A[(size_t)(m0 + arow) * K + (k0) + ak4]); \
            cpa16(&As_[(arow + 64) * APAD + ak4], &A[(size_t)(m0 + arow + 64) * K + (k0) + ak4]); \
            const float* wb_ = W + ((size_t)((k0) >> 4) * N + n0 + tid) * 16;          \
            cpa16(&Bs_[tid * APAD + 0],  wb_ + 0);                                     \
            cpa16(&Bs_[tid * APAD + 4],  wb_ + 4);                                     \
            cpa16(&Bs_[tid * APAD + 8],  wb_ + 8);                                     \
            cpa16(&Bs_[tid * APAD + 12], wb_ + 12);                                    \
            asm volatile("cp.async.commit_group;");                                    \
        } while (0)

    LOAD_STAGE(0, 0);
    LOAD_STAGE(1, GBK);
    LOAD_STAGE(2, 2 * GBK);

    for (int kt = 0; kt < nK; kt++) {
        asm volatile("cp.async.wait_group 2;");
        __syncthreads();
        const int st = kt & 3;
        if (kt + 3 < nK) LOAD_STAGE((kt + 3) & 3, (kt + 3) * GBK);

        const uint32_t aoff = st * (ASTG * 4);
        const uint32_t boff = st * (BSTG * 4);
        #pragma unroll
        for (int kk = 0; kk < GBK; kk += 8) {
            uint32_t af[4][4], bq[4][4];
            #pragma unroll
            for (int mt = 0; mt < 4; mt++) LDSM4(af[mt], aAddr[mt] + aoff + kk * 4);
            #pragma unroll
            for (int p = 0; p < 4; p++)    LDSM4(bq[p],  bAddr[p] + boff + kk * 4);
            #pragma unroll
            for (int mt = 0; mt < 4; mt++)
                #pragma unroll
                for (int nt = 0; nt < 8; nt++)
                    mma_tf32(acc[mt][nt], af[mt], &bq[nt >> 1][(nt & 1) * 2]);
        }
        __syncthreads();
    }
    #undef LOAD_STAGE

    #pragma unroll
    for (int mt = 0; mt < 4; mt++) {
        int r0 = m0 + wm + mt * 16 + gid;
        #pragma unroll
        for (int nt = 0; nt < 8; nt++) {
            int col = n0 + wn + nt * 8 + tig * 2;
            const float* bp = b0p;
            int bcol = col;
            if (NBSEL == 3) {
                int sel = col >> 10;
                bp = (sel == 0) ? b0p : (sel == 1 ? b1p : b2p);
                bcol = col & 1023;
            }
            float bb0 = bp[bcol], bb1 = bp[bcol + 1];
            float v0 = acc[mt][nt][0] + bb0, v1 = acc[mt][nt][1] + bb1;
            float v2 = acc[mt][nt][2] + bb0, v3 = acc[mt][nt][3] + bb1;
            if (RELU) {
                v0 = fmaxf(v0, 0.f); v1 = fmaxf(v1, 0.f);
                v2 = fmaxf(v2, 0.f); v3 = fmaxf(v3, 0.f);
            }
            if (ROUND) {
                v0 = __uint_as_float(f2tf(v0)); v1 = __uint_as_float(f2tf(v1));
                v2 = __uint_as_float(f2tf(v2)); v3 = __uint_as_float(f2tf(v3));
            }
            *(float2*)&C[(size_t)r0 * N + col]       = make_float2(v0, v1);
            *(float2*)&C[(size_t)(r0 + 8) * N + col] = make_float2(v2, v3);
        }
    }
}

// ---------------- flash attention on tensor cores (TF32, HD=64) ------------
// Q/K/V row strides parametrized (fused QKV/KV buffers). Output rounded tf32.
#define FL_SMEM (2*64*68*4 + 2*64*72*4)   /* 71680 bytes */

template <bool CAUSAL>
__global__ __launch_bounds__(256)
void flash_mma_kernel(const float* __restrict__ Q, int qrs,
                      const float* __restrict__ Kg, const float* __restrict__ Vg, int krs,
                      float* __restrict__ O, int Slen) {
    extern __shared__ float fsm[];
    float (*Ks)[64][68] = (float (*)[64][68])fsm;
    float (*Vs)[64][72] = (float (*)[64][72])(fsm + 2 * 64 * 68);

    const int tid = threadIdx.x, warp = tid >> 5, lane = tid & 31;
    const int gid = lane >> 2, tig = lane & 3;
    const int bh = blockIdx.y, b = bh >> 4, h = bh & 15;
    const int l0 = blockIdx.x * 128;
    const int col = h * HD_;
    const int rw = l0 + warp * 16;

    uint32_t qf[8][4];
    {
        const float* q0 = &Q[((size_t)(rw + gid) * B_ + b) * qrs + col];
        const float* q1 = &Q[((size_t)(rw + gid + 8) * B_ + b) * qrs + col];
        #pragma unroll
        for (int kk = 0; kk < 8; kk++) {
            qf[kk][0] = __float_as_uint(q0[kk * 8 + tig] * 0.125f);
            qf[kk][1] = __float_as_uint(q1[kk * 8 + tig] * 0.125f);
            qf[kk][2] = __float_as_uint(q0[kk * 8 + tig + 4] * 0.125f);
            qf[kk][3] = __float_as_uint(q1[kk * 8 + tig + 4] * 0.125f);
        }
    }

    float of[8][4];
    #pragma unroll
    for (int nt = 0; nt < 8; nt++)
        of[nt][0] = of[nt][1] = of[nt][2] = of[nt][3] = 0.f;
    float m0 = -1e30f, m1 = -1e30f, la0 = 0.f, la1 = 0.f;

    const int T = CAUSAL ? (l0 / 64 + 2) : (Slen / 64);

    {
        #pragma unroll
        for (int i = 0; i < 4; i++) {
            int idx = tid + i * 256;
            int r = idx >> 4, c4 = (idx & 15) * 4;
            size_t goff = ((size_t)r * B_ + b) * krs + col + c4;
            cpa16(&Ks[0][r][c4], &Kg[goff]);
            cpa16(&Vs[0][r][c4], &Vg[goff]);
        }
        asm volatile("cp.async.commit_group;");
    }

    for (int t = 0; t < T; t++) {
        const int bf = t & 1;
        if (t + 1 < T) {
            const int s1 = (t + 1) * 64, b2 = bf ^ 1;
            #pragma unroll
            for (int i = 0; i < 4; i++) {
                int idx = tid + i * 256;
                int r = idx >> 4, c4 = (idx & 15) * 4;
                size_t goff = ((size_t)(s1 + r) * B_ + b) * krs + col + c4;
                cpa16(&Ks[b2][r][c4], &Kg[goff]);
                cpa16(&Vs[b2][r][c4], &Vg[goff]);
            }
            asm volatile("cp.async.commit_group;");
            asm volatile("cp.async.wait_group 1;");
        } else {
            asm volatile("cp.async.wait_group 0;");
        }
        __syncthreads();

        const int s0 = t * 64;
        if (!CAUSAL || s0 <= rw) {
            float sf[8][4];
            #pragma unroll
            for (int nt = 0; nt < 8; nt++)
                sf[nt][0] = sf[nt][1] = sf[nt][2] = sf[nt][3] = 0.f;
            #pragma unroll
            for (int kk = 0; kk < 8; kk++) {
                #pragma unroll
                for (int nt = 0; nt < 8; nt++) {
                    uint32_t bb[2];
                    bb[0] = __float_as_uint(Ks[bf][nt * 8 + gid][kk * 8 + tig]);
                    bb[1] = __float_as_uint(Ks[bf][nt * 8 + gid][kk * 8 + tig + 4]);
                    mma_tf32(sf[nt], qf[kk], bb);
                }
            }
            if (CAUSAL && s0 + 63 > rw) {
                int r0 = rw + gid, r1 = r0 + 8;
                #pragma unroll
                for (int nt = 0; nt < 8; nt++) {
                    int c = s0 + nt * 8 + 2 * tig;
                    if (c     > r0) sf[nt][0] = -1e30f;
                    if (c + 1 > r0) sf[nt][1] = -1e30f;
                    if (c     > r1) sf[nt][2] = -1e30f;
                    if (c + 1 > r1) sf[nt][3] = -1e30f;
                }
            }
            float mx0 = -1e30f, mx1 = -1e30f;
            #pragma unroll
            for (int nt = 0; nt < 8; nt++) {
                mx0 = fmaxf(mx0, fmaxf(sf[nt][0], sf[nt][1]));
                mx1 = fmaxf(mx1, fmaxf(sf[nt][2], sf[nt][3]));
            }
            mx0 = fmaxf(mx0, __shfl_xor_sync(0xffffffffu, mx0, 1));
            mx0 = fmaxf(mx0, __shfl_xor_sync(0xffffffffu, mx0, 2));
            mx1 = fmaxf(mx1, __shfl_xor_sync(0xffffffffu, mx1, 1));
            mx1 = fmaxf(mx1, __shfl_xor_sync(0xffffffffu, mx1, 2));
            float mn0 = fmaxf(m0, mx0), mn1 = fmaxf(m1, mx1);
            float f0 = __expf(m0 - mn0), f1 = __expf(m1 - mn1);
            m0 = mn0;  m1 = mn1;
            float ss0 = 0.f, ss1 = 0.f;
            #pragma unroll
            for (int nt = 0; nt < 8; nt++) {
                sf[nt][0] = __expf(sf[nt][0] - m0);  ss0 += sf[nt][0];
                sf[nt][1] = __expf(sf[nt][1] - m0);  ss0 += sf[nt][1];
                sf[nt][2] = __expf(sf[nt][2] - m1);  ss1 += sf[nt][2];
                sf[nt][3] = __expf(sf[nt][3] - m1);  ss1 += sf[nt][3];
            }
            ss0 += __shfl_xor_sync(0xffffffffu, ss0, 1);
            ss0 += __shfl_xor_sync(0xffffffffu, ss0, 2);
            ss1 += __shfl_xor_sync(0xffffffffu, ss1, 1);
            ss1 += __shfl_xor_sync(0xffffffffu, ss1, 2);
            la0 = la0 * f0 + ss0;
            la1 = la1 * f1 + ss1;
            #pragma unroll
            for (int nt = 0; nt < 8; nt++) {
                of[nt][0] *= f0;  of[nt][1] *= f0;
                of[nt][2] *= f1;  of[nt][3] *= f1;
            }
            const int src0 = (lane & ~3) | (tig >> 1);
            const bool odd = (tig & 1) != 0;
            #pragma unroll
            for (int kk = 0; kk < 8; kk++) {
                float v0 = __shfl_sync(0xffffffffu, sf[kk][0], src0);
                float v1 = __shfl_sync(0xffffffffu, sf[kk][1], src0);
                float v2 = __shfl_sync(0xffffffffu, sf[kk][2], src0);
                float v3 = __shfl_sync(0xffffffffu, sf[kk][3], src0);
                float w0 = __shfl_sync(0xffffffffu, sf[kk][0], src0 + 2);
                float w1 = __shfl_sync(0xffffffffu, sf[kk][1], src0 + 2);
                float w2 = __shfl_sync(0xffffffffu, sf[kk][2], src0 + 2);
                float w3 = __shfl_sync(0xffffffffu, sf[kk][3], src0 + 2);
                uint32_t a[4];
                a[0] = f2tf(odd ? v1 : v0);
                a[1] = f2tf(odd ? v3 : v2);
                a[2] = f2tf(odd ? w1 : w0);
                a[3] = f2tf(odd ? w3 : w2);
                #pragma unroll
                for (int nt = 0; nt < 8; nt++) {
                    uint32_t bb[2];
                    bb[0] = __float_as_uint(Vs[bf][kk * 8 + tig][nt * 8 + gid]);
                    bb[1] = __float_as_uint(Vs[bf][kk * 8 + tig + 4][nt * 8 + gid]);
                    mma_tf32(of[nt], a, bb);
                }
            }
        }
        __syncthreads();
    }

    const float inv0 = 1.f / la0, inv1 = 1.f / la1;
    const int r0 = rw + gid, r1 = r0 + 8;
    #pragma unroll
    for (int nt = 0; nt < 8; nt++) {
        int c = col + nt * 8 + 2 * tig;
        *(float2*)&O[((size_t)r0 * B_ + b) * E_ + c] =
            make_float2(__uint_as_float(f2tf(of[nt][0] * inv0)),
                        __uint_as_float(f2tf(of[nt][1] * inv0)));
        *(float2*)&O[((size_t)r1 * B_ + b) * E_ + c] =
            make_float2(__uint_as_float(f2tf(of[nt][2] * inv1)),
                        __uint_as_float(f2tf(of[nt][3] * inv1)));
    }
}

// ---------------- fused residual + LayerNorm (+opt rounded twin) -----------
template <bool WR>
__global__ __launch_bounds__(256)
void add_ln_kernel(const float* __restrict__ A, const float* __restrict__ Bb,
                   const float* __restrict__ g, const float* __restrict__ be,
                   float* __restrict__ out, float* __restrict__ outR) {
    __shared__ float rbuf[8];
    __shared__ float stat;
    int row = blockIdx.x, tid = threadIdx.x, lane = tid & 31, warp = tid >> 5;
    size_t base = (size_t)row * E_ + tid * 4;

    float4 a = *(const float4*)&A[base];
    float4 b = *(const float4*)&Bb[base];
    float4 x = make_float4(a.x + b.x, a.y + b.y, a.z + b.z, a.w + b.w);

    float s = x.x + x.y + x.z + x.w;
    #pragma unroll
    for (int off = 16; off > 0; off >>= 1) s += __shfl_xor_sync(0xffffffffu, s, off);
    if (lane == 0) rbuf[warp] = s;
    __syncthreads();
    if (tid == 0) {
        float t = 0.f;
        #pragma unroll
        for (int i = 0; i < 8; i++) t += rbuf[i];
        stat = t * (1.0f / E_);
    }
    __syncthreads();
    float mu = stat;

    float4 dx = make_float4(x.x - mu, x.y - mu, x.z - mu, x.w - mu);
    float sq = dx.x * dx.x + dx.y * dx.y + dx.z * dx.z + dx.w * dx.w;
    #pragma unroll
    for (int off = 16; off > 0; off >>= 1) sq += __shfl_xor_sync(0xffffffffu, sq, off);
    if (lane == 0) rbuf[warp] = sq;
    __syncthreads();
    if (tid == 0) {
        float t = 0.f;
        #pragma unroll
        for (int i = 0; i < 8; i++) t += rbuf[i];
        stat = rsqrtf(t * (1.0f / E_) + EPS_);
    }
    __syncthreads();
    float rs = stat;

    float4 gv = *(const float4*)&g[tid * 4];
    float4 bv = *(const float4*)&be[tid * 4];
    float4 y = make_float4(dx.x * rs * gv.x + bv.x, dx.y * rs * gv.y + bv.y,
                           dx.z * rs * gv.z + bv.z, dx.w * rs * gv.w + bv.w);
    *(float4*)&out[base] = y;
    if (WR) {
        float4 yr = make_float4(__uint_as_float(f2tf(y.x)), __uint_as_float(f2tf(y.y)),
                                __uint_as_float(f2tf(y.z)), __uint_as_float(f2tf(y.w)));
        *(float4*)&outR[base] = yr;
    }
}

// ---------------- launcher ------------------------------------------------
extern "C" void kernel_launch(void* const* d_in, const int* in_sizes, int n_in,
                              void* d_out, int out_size) {
    (void)in_sizes; (void)n_in; (void)out_size;
    const float* tgt  = (const float*)d_in[0];
    const float* memi = (const float*)d_in[1];
    // d_in[2] = tgt_mask: strictly causal by construction; causal predicate used instead.
    const float* saWq = (const float*)d_in[3];  const float* sabq = (const float*)d_in[4];
    const float* saWk = (const float*)d_in[5];  const float* sabk = (const float*)d_in[6];
    const float* saWv = (const float*)d_in[7];  const float* sabv = (const float*)d_in[8];
    const float* saWo = (const float*)d_in[9];  const float* sabo = (const float*)d_in[10];
    const float* caWq = (const float*)d_in[11]; const float* cabq = (const float*)d_in[12];
    const float* caWk = (const float*)d_in[13]; const float* cabk = (const float*)d_in[14];
    const float* caWv = (const float*)d_in[15]; const float* cabv = (const float*)d_in[16];
    const float* caWo = (const float*)d_in[17]; const float* cabo = (const float*)d_in[18];
    const float* W1   = (const float*)d_in[19]; const float* b1   = (const float*)d_in[20];
    const float* W2   = (const float*)d_in[21]; const float* b2   = (const float*)d_in[22];
    const float* ln1g = (const float*)d_in[23]; const float* ln1b = (const float*)d_in[24];
    const float* ln2g = (const float*)d_in[25]; const float* ln2b = (const float*)d_in[26];
    const float* ln3g = (const float*)d_in[27]; const float* ln3b = (const float*)d_in[28];

    float *qkv, *q, *kv, *ao, *t, *x1, *x2, *x1r, *x2r, *tr, *mr, *hh, *wt;
    cudaGetSymbolAddress((void**)&qkv, g_qkv);
    cudaGetSymbolAddress((void**)&q,   g_q);
    cudaGetSymbolAddress((void**)&kv,  g_kv);
    cudaGetSymbolAddress((void**)&ao,  g_ao);
    cudaGetSymbolAddress((void**)&t,   g_t);
    cudaGetSymbolAddress((void**)&x1,  g_x1);
    cudaGetSymbolAddress((void**)&x2,  g_x2);
    cudaGetSymbolAddress((void**)&x1r, g_x1r);
    cudaGetSymbolAddress((void**)&x2r, g_x2r);
    cudaGetSymbolAddress((void**)&tr,  g_tr);
    cudaGetSymbolAddress((void**)&mr,  g_mr);
    cudaGetSymbolAddress((void**)&hh,  g_h);
    cudaGetSymbolAddress((void**)&wt,  g_wt);

    cudaFuncSetAttribute(flash_mma_kernel<true>,
                         cudaFuncAttributeMaxDynamicSharedMemorySize, FL_SMEM);
    cudaFuncSetAttribute(flash_mma_kernel<false>,
                         cudaFuncAttributeMaxDynamicSharedMemorySize, FL_SMEM);
    cudaFuncSetAttribute(gemm_tf32_kernel<false, true, 3>,
                         cudaFuncAttributeMaxDynamicSharedMemorySize, GEMM_SMEM);
    cudaFuncSetAttribute(gemm_tf32_kernel<false, true, 1>,
                         cudaFuncAttributeMaxDynamicSharedMemorySize, GEMM_SMEM);
    cudaFuncSetAttribute(gemm_tf32_kernel<false, false, 1>,
                         cudaFuncAttributeMaxDynamicSharedMemorySize, GEMM_SMEM);
    cudaFuncSetAttribute(gemm_tf32_kernel<true, true, 1>,
                         cudaFuncAttributeMaxDynamicSharedMemorySize, GEMM_SMEM);

    // blocked weight buffers (16M floats total)
    float* wqkv  = wt;                    // 3072x1024
    float* wsao  = wt + 3 * E_ * E_;      // 1024x1024
    float* wcaq  = wt + 4 * E_ * E_;      // 1024x1024
    float* wcakv = wt + 5 * E_ * E_;      // 2048x1024
    float* wcao  = wt + 7 * E_ * E_;      // 1024x1024
    float* ww1   = wt + 8 * E_ * E_;      // 4096x1024
    float* ww2   = wt + 8 * E_ * E_ + E_ * FF_;  // 1024x4096

    const int RT = 256;
    const int nEE  = E_ * E_ / 4;
    const int nEFF = E_ * FF_ / 4;
    const int nME  = M_ * E_ / 4;
    dim3 gQKV(3 * E_ / GBN, M_ / GBM);   // (12, 64)
    dim3 gKV (2 * E_ / GBN, M_ / GBM);   // (8, 64)
    dim3 g1  (E_ / GBN, M_ / GBM);       // (4, 64)
    dim3 gF1 (FF_ / GBN, M_ / GBM);      // (16, 64)
    dim3 ga  (L_ / 128, B_ * H_);        // (16, 64)

    // ---- prep (self-attn) ----
    round_tf32_kernel<<<(nME + RT - 1) / RT, RT>>>(tgt, tr, nME);
    pack_w_kernel<<<(nEE + RT - 1) / RT, RT>>>(saWq, wqkv, 0,    3 * E_, E_, E_);
    pack_w_kernel<<<(nEE + RT - 1) / RT, RT>>>(saWk, wqkv, E_,   3 * E_, E_, E_);
    pack_w_kernel<<<(nEE + RT - 1) / RT, RT>>>(saWv, wqkv, 2*E_, 3 * E_, E_, E_);
    pack_w_kernel<<<(nEE + RT - 1) / RT, RT>>>(saWo, wsao, 0,    E_,     E_, E_);

    // ---- self attention block ----
    gemm_tf32_kernel<false, true, 3><<<gQKV, 256, GEMM_SMEM>>>(
        tr, wqkv, sabq, sabk, sabv, qkv, M_, 3 * E_, E_);
    flash_mma_kernel<true><<<ga, 256, FL_SMEM>>>(
        qkv, 3 * E_, qkv + E_, qkv + 2 * E_, 3 * E_, ao, L_);
    gemm_tf32_kernel<false, false, 1><<<g1, 256, GEMM_SMEM>>>(
        ao, wsao, sabo, sabo, sabo, t, M_, E_, E_);
    add_ln_kernel<true><<<M_, 256>>>(tgt, t, ln1g, ln1b, x1, x1r);

    // ---- prep (cross-attn, FFN) ----
    round_tf32_kernel<<<(nME + RT - 1) / RT, RT>>>(memi, mr, nME);
    pack_w_kernel<<<(nEE + RT - 1) / RT, RT>>>(caWq, wcaq,  0,  E_,     E_, E_);
    pack_w_kernel<<<(nEE + RT - 1) / RT, RT>>>(caWk, wcakv, 0,  2 * E_, E_, E_);
    pack_w_kernel<<<(nEE + RT - 1) / RT, RT>>>(caWv, wcakv, E_, 2 * E_, E_, E_);
    pack_w_kernel<<<(nEE + RT - 1) / RT, RT>>>(caWo, wcao,  0,  E_,     E_, E_);
    pack_w_kernel<<<(nEFF + RT - 1) / RT, RT>>>(W1, ww1, 0, FF_, FF_, E_);
    pack_w_kernel<<<(nEFF + RT - 1) / RT, RT>>>(W2, ww2, 0, E_,  E_,  FF_);

    // ---- cross attention block ----
    gemm_tf32_kernel<false, true, 1><<<g1, 256, GEMM_SMEM>>>(
        x1r, wcaq, cabq, cabq, cabq, q, M_, E_, E_);
    gemm_tf32_kernel<false, true, 3><<<gKV, 256, GEMM_SMEM>>>(
        mr, wcakv, cabk, cabv, cabv, kv, M_, 2 * E_, E_);
    flash_mma_kernel<false><<<ga, 256, FL_SMEM>>>(
        q, E_, kv, kv + E_, 2 * E_, ao, S_);
    gemm_tf32_kernel<false, false, 1><<<g1, 256, GEMM_SMEM>>>(
        ao, wcao, cabo, cabo, cabo, t, M_, E_, E_);
    add_ln_kernel<true><<<M_, 256>>>(x1, t, ln2g, ln2b, x2, x2r);

    // ---- FFN block ----
    gemm_tf32_kernel<true, true, 1><<<gF1, 256, GEMM_SMEM>>>(
        x2r, ww1, b1, b1, b1, hh, M_, FF_, E_);
    gemm_tf32_kernel<false, false, 1><<<g1, 256, GEMM_SMEM>>>(
        hh, ww2, b2, b2, b2, t, M_, E_, FF_);
    add_ln_kernel<false><<<M_, 256>>>(x2, t, ln3g, ln3b, (float*)d_out, nullptr);
}

// round 9
// speedup vs baseline: 1.7661x; 1.6915x over previous
#include <cuda_runtime.h>
#include <cuda_fp16.h>
#include <cstdint>

#define L_  2048
#define S_  2048
#define B_  4
#define E_  1024
#define H_  16
#define HD_ 64
#define FF_ 4096
#define M_  (L_*B_)
#define EPS_ 1e-5f

// ---------------- device scratch ------------------------------------------
__device__ float  g_qkv[M_*3*E_];
__device__ float  g_q  [M_*E_];
__device__ float  g_kv [M_*2*E_];
__device__ __half g_ao [M_*E_];
__device__ float  g_t  [M_*E_];
__device__ float  g_x1 [M_*E_];
__device__ float  g_x2 [M_*E_];
__device__ __half g_x1h[M_*E_];
__device__ __half g_x2h[M_*E_];
__device__ __half g_tgh[M_*E_];
__device__ __half g_meh[M_*E_];
__device__ __half g_hh [M_*FF_];
__device__ __half g_wh [8*E_*E_ + 2*E_*FF_];   /* 16M halves = 32MB */

// ---------------- PTX helpers ---------------------------------------------
__device__ __forceinline__ uint32_t f2tf(float x) {
    uint32_t r;
    asm("cvt.rna.tf32.f32 %0, %1;" : "=r"(r) : "f"(x));
    return r;
}
__device__ __forceinline__ uint32_t h2_bits(__half2 h) {
    uint32_t u;
    asm("mov.b32 %0, %1;" : "=r"(u) : "r"(*(uint32_t*)&h));
    return u;
}
__device__ __forceinline__ void cpa16(void* smem, const void* gmem) {
    uint32_t s = (uint32_t)__cvta_generic_to_shared(smem);
    asm volatile("cp.async.cg.shared.global [%0], [%1], 16;" :: "r"(s), "l"(gmem));
}
__device__ __forceinline__ void mma_tf32(float* d, const uint32_t* a, const uint32_t* b) {
    asm volatile(
        "mma.sync.aligned.m16n8k8.row.col.f32.tf32.tf32.f32 "
        "{%0,%1,%2,%3}, {%4,%5,%6,%7}, {%8,%9}, {%0,%1,%2,%3};"
        : "+f"(d[0]), "+f"(d[1]), "+f"(d[2]), "+f"(d[3])
        : "r"(a[0]), "r"(a[1]), "r"(a[2]), "r"(a[3]), "r"(b[0]), "r"(b[1]));
}
__device__ __forceinline__ void mma_f16(float* d, const uint32_t* a, const uint32_t* b) {
    asm volatile(
        "mma.sync.aligned.m16n8k16.row.col.f32.f16.f16.f32 "
        "{%0,%1,%2,%3}, {%4,%5,%6,%7}, {%8,%9}, {%0,%1,%2,%3};"
        : "+f"(d[0]), "+f"(d[1]), "+f"(d[2]), "+f"(d[3])
        : "r"(a[0]), "r"(a[1]), "r"(a[2]), "r"(a[3]), "r"(b[0]), "r"(b[1]));
}

// ---------------- f32 -> f16 convert ---------------------------------------
__global__ void cvt_h_kernel(const float* __restrict__ in,
                             __half* __restrict__ out, int n4) {
    int i = blockIdx.x * blockDim.x + threadIdx.x;
    if (i < n4) {
        float4 v = *(const float4*)&in[i * 4];
        __half2 h0 = __floats2half2_rn(v.x, v.y);
        __half2 h1 = __floats2half2_rn(v.z, v.w);
        *(uint2*)&out[i * 4] = make_uint2(h2_bits(h0), h2_bits(h1));
    }
}

// ---------------- FP16 tensor-core GEMM ------------------------------------
// C[M,N] = A[M,K] @ W^T + bias ; A,W fp16 (W native [N,K], pre-fused/contig).
// 128x256 tile, BK=32, 8 warps (2x4), warp 64x64, m16n8k16, 3-stage cp.async.
#define GBM 128
#define GBN 256
#define GBK 32
#define HPAD 40                       /* halves per row in smem */
#define ASTGH (GBM*HPAD)              /* 5120 halves  */
#define BSTGH (GBN*HPAD)              /* 10240 halves */
#define NSTG 3
#define GEMM_SMEM (NSTG*(ASTGH+BSTGH)*2)   /* 92160 bytes */

template <bool RELU, int NBSEL, bool HOUT>
__global__ __launch_bounds__(256, 1)
void gemm_f16(const __half* __restrict__ A, const __half* __restrict__ W,
              const float* __restrict__ bb0, const float* __restrict__ bb1,
              const float* __restrict__ bb2, void* __restrict__ Cv,
              int N, int K) {
    extern __shared__ __half sm[];
    const int tid  = threadIdx.x;
    const int lane = tid & 31, warp = tid >> 5;
    const int gid  = lane >> 2, tig = lane & 3;
    const int wm   = (warp & 1) * 64;
    const int wn   = (warp >> 1) * 64;
    const int m0   = blockIdx.y * GBM, n0 = blockIdx.x * GBN;

    float acc[4][8][4];
    #pragma unroll
    for (int mt = 0; mt < 4; mt++)
        #pragma unroll
        for (int nt = 0; nt < 8; nt++)
            #pragma unroll
            for (int i = 0; i < 4; i++) acc[mt][nt][i] = 0.0f;

    const int nC = K / GBK;

    #define LOAD_STAGE(s, k0)                                                      \
        do {                                                                       \
            __half* As_ = sm + (s) * ASTGH;                                        \
            __half* Bs_ = sm + NSTG * ASTGH + (s) * BSTGH;                         \
            _Pragma("unroll")                                                      \
            for (int i = 0; i < 2; i++) {                                          \
                int u = tid + i * 256, row = u >> 2, ch = (u & 3) * 8;             \
                cpa16(&As_[row * HPAD + ch],                                       \
                      A + (size_t)(m0 + row) * K + (k0) + ch);                     \
            }                                                                      \
            _Pragma("unroll")                                                      \
            for (int i = 0; i < 4; i++) {                                          \
                int u = tid + i * 256, row = u >> 2, ch = (u & 3) * 8;             \
                cpa16(&Bs_[row * HPAD + ch],                                       \
                      W + (size_t)(n0 + row) * K + (k0) + ch);                     \
            }                                                                      \
            asm volatile("cp.async.commit_group;");                                \
        } while (0)

    LOAD_STAGE(0, 0);
    LOAD_STAGE(1, GBK);

    for (int kt = 0; kt < nC; kt++) {
        asm volatile("cp.async.wait_group 1;");
        __syncthreads();
        const int st = kt % 3;
        if (kt + 2 < nC) LOAD_STAGE((kt + 2) % 3, (kt + 2) * GBK);

        const __half* As_ = sm + st * ASTGH;
        const __half* Bs_ = sm + NSTG * ASTGH + st * BSTGH;
        #pragma unroll
        for (int kk = 0; kk < GBK; kk += 16) {
            uint32_t af[4][4], bf[8][2];
            #pragma unroll
            for (int mt = 0; mt < 4; mt++) {
                int mr = wm + mt * 16 + gid;
                af[mt][0] = *(const uint32_t*)&As_[mr * HPAD + kk + 2 * tig];
                af[mt][1] = *(const uint32_t*)&As_[(mr + 8) * HPAD + kk + 2 * tig];
                af[mt][2] = *(const uint32_t*)&As_[mr * HPAD + kk + 2 * tig + 8];
                af[mt][3] = *(const uint32_t*)&As_[(mr + 8) * HPAD + kk + 2 * tig + 8];
            }
            #pragma unroll
            for (int nt = 0; nt < 8; nt++) {
                int nc = wn + nt * 8 + gid;
                bf[nt][0] = *(const uint32_t*)&Bs_[nc * HPAD + kk + 2 * tig];
                bf[nt][1] = *(const uint32_t*)&Bs_[nc * HPAD + kk + 2 * tig + 8];
            }
            #pragma unroll
            for (int mt = 0; mt < 4; mt++)
                #pragma unroll
                for (int nt = 0; nt < 8; nt++)
                    mma_f16(acc[mt][nt], af[mt], bf[nt]);
        }
        __syncthreads();
    }
    #undef LOAD_STAGE

    #pragma unroll
    for (int mt = 0; mt < 4; mt++) {
        int r0 = m0 + wm + mt * 16 + gid;
        #pragma unroll
        for (int nt = 0; nt < 8; nt++) {
            int col = n0 + wn + nt * 8 + tig * 2;
            const float* bp = bb0;
            int bcol = col;
            if (NBSEL == 3) {
                int sel = col >> 10;
                bp = (sel == 0) ? bb0 : (sel == 1 ? bb1 : bb2);
                bcol = col & 1023;
            }
            float bv0 = bp[bcol], bv1 = bp[bcol + 1];
            float v0 = acc[mt][nt][0] + bv0, v1 = acc[mt][nt][1] + bv1;
            float v2 = acc[mt][nt][2] + bv0, v3 = acc[mt][nt][3] + bv1;
            if (RELU) {
                v0 = fmaxf(v0, 0.f); v1 = fmaxf(v1, 0.f);
                v2 = fmaxf(v2, 0.f); v3 = fmaxf(v3, 0.f);
            }
            if (HOUT) {
                __half* C = (__half*)Cv;
                __half2 o0 = __floats2half2_rn(v0, v1);
                __half2 o1 = __floats2half2_rn(v2, v3);
                *(uint32_t*)&C[(size_t)r0 * N + col]       = h2_bits(o0);
                *(uint32_t*)&C[(size_t)(r0 + 8) * N + col] = h2_bits(o1);
            } else {
                float* C = (float*)Cv;
                *(float2*)&C[(size_t)r0 * N + col]       = make_float2(v0, v1);
                *(float2*)&C[(size_t)(r0 + 8) * N + col] = make_float2(v2, v3);
            }
        }
    }
}

// ---------------- flash attention (mma.sync TF32, HD=64) -------------------
// f32 Q/K/V inputs (strided); fp16 output for the out-projection GEMM.
#define FL_SMEM (2*64*68*4 + 2*64*72*4)

template <bool CAUSAL>
__global__ __launch_bounds__(256)
void flash_mma_kernel(const float* __restrict__ Q, int qrs,
                      const float* __restrict__ Kg, const float* __restrict__ Vg, int krs,
                      __half* __restrict__ O, int Slen) {
    extern __shared__ float fsm[];
    float (*Ks)[64][68] = (float (*)[64][68])fsm;
    float (*Vs)[64][72] = (float (*)[64][72])(fsm + 2 * 64 * 68);

    const int tid = threadIdx.x, warp = tid >> 5, lane = tid & 31;
    const int gid = lane >> 2, tig = lane & 3;
    const int bh = blockIdx.y, b = bh >> 4, h = bh & 15;
    const int l0 = blockIdx.x * 128;
    const int col = h * HD_;
    const int rw = l0 + warp * 16;

    uint32_t qf[8][4];
    {
        const float* q0 = &Q[((size_t)(rw + gid) * B_ + b) * qrs + col];
        const float* q1 = &Q[((size_t)(rw + gid + 8) * B_ + b) * qrs + col];
        #pragma unroll
        for (int kk = 0; kk < 8; kk++) {
            qf[kk][0] = __float_as_uint(q0[kk * 8 + tig] * 0.125f);
            qf[kk][1] = __float_as_uint(q1[kk * 8 + tig] * 0.125f);
            qf[kk][2] = __float_as_uint(q0[kk * 8 + tig + 4] * 0.125f);
            qf[kk][3] = __float_as_uint(q1[kk * 8 + tig + 4] * 0.125f);
        }
    }

    float of[8][4];
    #pragma unroll
    for (int nt = 0; nt < 8; nt++)
        of[nt][0] = of[nt][1] = of[nt][2] = of[nt][3] = 0.f;
    float m0 = -1e30f, m1 = -1e30f, la0 = 0.f, la1 = 0.f;

    const int T = CAUSAL ? (l0 / 64 + 2) : (Slen / 64);

    {
        #pragma unroll
        for (int i = 0; i < 4; i++) {
            int idx = tid + i * 256;
            int r = idx >> 4, c4 = (idx & 15) * 4;
            size_t goff = ((size_t)r * B_ + b) * krs + col + c4;
            cpa16(&Ks[0][r][c4], &Kg[goff]);
            cpa16(&Vs[0][r][c4], &Vg[goff]);
        }
        asm volatile("cp.async.commit_group;");
    }

    for (int t = 0; t < T; t++) {
        const int bf = t & 1;
        if (t + 1 < T) {
            const int s1 = (t + 1) * 64, b2 = bf ^ 1;
            #pragma unroll
            for (int i = 0; i < 4; i++) {
                int idx = tid + i * 256;
                int r = idx >> 4, c4 = (idx & 15) * 4;
                size_t goff = ((size_t)(s1 + r) * B_ + b) * krs + col + c4;
                cpa16(&Ks[b2][r][c4], &Kg[goff]);
                cpa16(&Vs[b2][r][c4], &Vg[goff]);
            }
            asm volatile("cp.async.commit_group;");
            asm volatile("cp.async.wait_group 1;");
        } else {
            asm volatile("cp.async.wait_group 0;");
        }
        __syncthreads();

        const int s0 = t * 64;
        if (!CAUSAL || s0 <= rw) {
            float sf[8][4];
            #pragma unroll
            for (int nt = 0; nt < 8; nt++)
                sf[nt][0] = sf[nt][1] = sf[nt][2] = sf[nt][3] = 0.f;
            #pragma unroll
            for (int kk = 0; kk < 8; kk++) {
                #pragma unroll
                for (int nt = 0; nt < 8; nt++) {
                    uint32_t bb[2];
                    bb[0] = __float_as_uint(Ks[bf][nt * 8 + gid][kk * 8 + tig]);
                    bb[1] = __float_as_uint(Ks[bf][nt * 8 + gid][kk * 8 + tig + 4]);
                    mma_tf32(sf[nt], qf[kk], bb);
                }
            }
            if (CAUSAL && s0 + 63 > rw) {
                int r0 = rw + gid, r1 = r0 + 8;
                #pragma unroll
                for (int nt = 0; nt < 8; nt++) {
                    int c = s0 + nt * 8 + 2 * tig;
                    if (c     > r0) sf[nt][0] = -1e30f;
                    if (c + 1 > r0) sf[nt][1] = -1e30f;
                    if (c     > r1) sf[nt][2] = -1e30f;
                    if (c + 1 > r1) sf[nt][3] = -1e30f;
                }
            }
            float mx0 = -1e30f, mx1 = -1e30f;
            #pragma unroll
            for (int nt = 0; nt < 8; nt++) {
                mx0 = fmaxf(mx0, fmaxf(sf[nt][0], sf[nt][1]));
                mx1 = fmaxf(mx1, fmaxf(sf[nt][2], sf[nt][3]));
            }
            mx0 = fmaxf(mx0, __shfl_xor_sync(0xffffffffu, mx0, 1));
            mx0 = fmaxf(mx0, __shfl_xor_sync(0xffffffffu, mx0, 2));
            mx1 = fmaxf(mx1, __shfl_xor_sync(0xffffffffu, mx1, 1));
            mx1 = fmaxf(mx1, __shfl_xor_sync(0xffffffffu, mx1, 2));
            float mn0 = fmaxf(m0, mx0), mn1 = fmaxf(m1, mx1);
            float f0 = __expf(m0 - mn0), f1 = __expf(m1 - mn1);
            m0 = mn0;  m1 = mn1;
            float ss0 = 0.f, ss1 = 0.f;
            #pragma unroll
            for (int nt = 0; nt < 8; nt++) {
                sf[nt][0] = __expf(sf[nt][0] - m0);  ss0 += sf[nt][0];
                sf[nt][1] = __expf(sf[nt][1] - m0);  ss0 += sf[nt][1];
                sf[nt][2] = __expf(sf[nt][2] - m1);  ss1 += sf[nt][2];
                sf[nt][3] = __expf(sf[nt][3] - m1);  ss1 += sf[nt][3];
            }
            ss0 += __shfl_xor_sync(0xffffffffu, ss0, 1);
            ss0 += __shfl_xor_sync(0xffffffffu, ss0, 2);
            ss1 += __shfl_xor_sync(0xffffffffu, ss1, 1);
            ss1 += __shfl_xor_sync(0xffffffffu, ss1, 2);
            la0 = la0 * f0 + ss0;
            la1 = la1 * f1 + ss1;
            #pragma unroll
            for (int nt = 0; nt < 8; nt++) {
                of[nt][0] *= f0;  of[nt][1] *= f0;
                of[nt][2] *= f1;  of[nt][3] *= f1;
            }
            const int src0 = (lane & ~3) | (tig >> 1);
            const bool odd = (tig & 1) != 0;
            #pragma unroll
            for (int kk = 0; kk < 8; kk++) {
                float v0 = __shfl_sync(0xffffffffu, sf[kk][0], src0);
                float v1 = __shfl_sync(0xffffffffu, sf[kk][1], src0);
                float v2 = __shfl_sync(0xffffffffu, sf[kk][2], src0);
                float v3 = __shfl_sync(0xffffffffu, sf[kk][3], src0);
                float w0 = __shfl_sync(0xffffffffu, sf[kk][0], src0 + 2);
                float w1 = __shfl_sync(0xffffffffu, sf[kk][1], src0 + 2);
                float w2 = __shfl_sync(0xffffffffu, sf[kk][2], src0 + 2);
                float w3 = __shfl_sync(0xffffffffu, sf[kk][3], src0 + 2);
                uint32_t a[4];
                a[0] = f2tf(odd ? v1 : v0);
                a[1] = f2tf(odd ? v3 : v2);
                a[2] = f2tf(odd ? w1 : w0);
                a[3] = f2tf(odd ? w3 : w2);
                #pragma unroll
                for (int nt = 0; nt < 8; nt++) {
                    uint32_t bb[2];
                    bb[0] = __float_as_uint(Vs[bf][kk * 8 + tig][nt * 8 + gid]);
                    bb[1] = __float_as_uint(Vs[bf][kk * 8 + tig + 4][nt * 8 + gid]);
                    mma_tf32(of[nt], a, bb);
                }
            }
        }
        __syncthreads();
    }

    const float inv0 = 1.f / la0, inv1 = 1.f / la1;
    const int r0 = rw + gid, r1 = r0 + 8;
    #pragma unroll
    for (int nt = 0; nt < 8; nt++) {
        int c = col + nt * 8 + 2 * tig;
        __half2 o0 = __floats2half2_rn(of[nt][0] * inv0, of[nt][1] * inv0);
        __half2 o1 = __floats2half2_rn(of[nt][2] * inv1, of[nt][3] * inv1);
        *(uint32_t*)&O[((size_t)r0 * B_ + b) * E_ + c] = h2_bits(o0);
        *(uint32_t*)&O[((size_t)r1 * B_ + b) * E_ + c] = h2_bits(o1);
    }
}

// ---------------- fused residual + LayerNorm (+opt fp16 twin) --------------
template <bool WH>
__global__ __launch_bounds__(256)
void add_ln_kernel(const float* __restrict__ A, const float* __restrict__ Bb,
                   const float* __restrict__ g, const float* __restrict__ be,
                   float* __restrict__ out, __half* __restrict__ outH) {
    __shared__ float rbuf[8];
    __shared__ float stat;
    int row = blockIdx.x, tid = threadIdx.x, lane = tid & 31, warp = tid >> 5;
    size_t base = (size_t)row * E_ + tid * 4;

    float4 a = *(const float4*)&A[base];
    float4 b = *(const float4*)&Bb[base];
    float4 x = make_float4(a.x + b.x, a.y + b.y, a.z + b.z, a.w + b.w);

    float s = x.x + x.y + x.z + x.w;
    #pragma unroll
    for (int off = 16; off > 0; off >>= 1) s += __shfl_xor_sync(0xffffffffu, s, off);
    if (lane == 0) rbuf[warp] = s;
    __syncthreads();
    if (tid == 0) {
        float t = 0.f;
        #pragma unroll
        for (int i = 0; i < 8; i++) t += rbuf[i];
        stat = t * (1.0f / E_);
    }
    __syncthreads();
    float mu = stat;

    float4 dx = make_float4(x.x - mu, x.y - mu, x.z - mu, x.w - mu);
    float sq = dx.x * dx.x + dx.y * dx.y + dx.z * dx.z + dx.w * dx.w;
    #pragma unroll
    for (int off = 16; off > 0; off >>= 1) sq += __shfl_xor_sync(0xffffffffu, sq, off);
    if (lane == 0) rbuf[warp] = sq;
    __syncthreads();
    if (tid == 0) {
        float t = 0.f;
        #pragma unroll
        for (int i = 0; i < 8; i++) t += rbuf[i];
        stat = rsqrtf(t * (1.0f / E_) + EPS_);
    }
    __syncthreads();
    float rs = stat;

    float4 gv = *(const float4*)&g[tid * 4];
    float4 bv = *(const float4*)&be[tid * 4];
    float4 y = make_float4(dx.x * rs * gv.x + bv.x, dx.y * rs * gv.y + bv.y,
                           dx.z * rs * gv.z + bv.z, dx.w * rs * gv.w + bv.w);
    *(float4*)&out[base] = y;
    if (WH) {
        __half2 h0 = __floats2half2_rn(y.x, y.y);
        __half2 h1 = __floats2half2_rn(y.z, y.w);
        *(uint2*)&outH[base] = make_uint2(h2_bits(h0), h2_bits(h1));
    }
}

// ---------------- launcher ------------------------------------------------
extern "C" void kernel_launch(void* const* d_in, const int* in_sizes, int n_in,
                              void* d_out, int out_size) {
    (void)in_sizes; (void)n_in; (void)out_size;
    const float* tgt  = (const float*)d_in[0];
    const float* memi = (const float*)d_in[1];
    // d_in[2] = tgt_mask: strictly causal by construction; causal predicate used instead.
    const float* saWq = (const float*)d_in[3];  const float* sabq = (const float*)d_in[4];
    const float* saWk = (const float*)d_in[5];  const float* sabk = (const float*)d_in[6];
    const float* saWv = (const float*)d_in[7];  const float* sabv = (const float*)d_in[8];
    const float* saWo = (const float*)d_in[9];  const float* sabo = (const float*)d_in[10];
    const float* caWq = (const float*)d_in[11]; const float* cabq = (const float*)d_in[12];
    const float* caWk = (const float*)d_in[13]; const float* cabk = (const float*)d_in[14];
    const float* caWv = (const float*)d_in[15]; const float* cabv = (const float*)d_in[16];
    const float* caWo = (const float*)d_in[17]; const float* cabo = (const float*)d_in[18];
    const float* W1   = (const float*)d_in[19]; const float* b1   = (const float*)d_in[20];
    const float* W2   = (const float*)d_in[21]; const float* b2   = (const float*)d_in[22];
    const float* ln1g = (const float*)d_in[23]; const float* ln1b = (const float*)d_in[24];
    const float* ln2g = (const float*)d_in[25]; const float* ln2b = (const float*)d_in[26];
    const float* ln3g = (const float*)d_in[27]; const float* ln3b = (const float*)d_in[28];

    float  *qkv, *q, *kv, *t, *x1, *x2;
    __half *ao, *x1h, *x2h, *tgh, *meh, *hh, *wh;
    cudaGetSymbolAddress((void**)&qkv, g_qkv);
    cudaGetSymbolAddress((void**)&q,   g_q);
    cudaGetSymbolAddress((void**)&kv,  g_kv);
    cudaGetSymbolAddress((void**)&ao,  g_ao);
    cudaGetSymbolAddress((void**)&t,   g_t);
    cudaGetSymbolAddress((void**)&x1,  g_x1);
    cudaGetSymbolAddress((void**)&x2,  g_x2);
    cudaGetSymbolAddress((void**)&x1h, g_x1h);
    cudaGetSymbolAddress((void**)&x2h, g_x2h);
    cudaGetSymbolAddress((void**)&tgh, g_tgh);
    cudaGetSymbolAddress((void**)&meh, g_meh);
    cudaGetSymbolAddress((void**)&hh,  g_hh);
    cudaGetSymbolAddress((void**)&wh,  g_wh);

    cudaFuncSetAttribute(flash_mma_kernel<true>,
                         cudaFuncAttributeMaxDynamicSharedMemorySize, FL_SMEM);
    cudaFuncSetAttribute(flash_mma_kernel<false>,
                         cudaFuncAttributeMaxDynamicSharedMemorySize, FL_SMEM);
    cudaFuncSetAttribute(gemm_f16<false, 3, false>,
                         cudaFuncAttributeMaxDynamicSharedMemorySize, GEMM_SMEM);
    cudaFuncSetAttribute(gemm_f16<false, 1, false>,
                         cudaFuncAttributeMaxDynamicSharedMemorySize, GEMM_SMEM);
    cudaFuncSetAttribute(gemm_f16<true, 1, true>,
                         cudaFuncAttributeMaxDynamicSharedMemorySize, GEMM_SMEM);

    // fp16 weight buffer layout (all native [N,K], fused groups contiguous)
    const int EE = E_ * E_, EFF = E_ * FF_;
    __half* whqkv  = wh;              // [3E, E]
    __half* whsao  = wh + 3 * EE;     // [E, E]
    __half* whcaq  = wh + 4 * EE;     // [E, E]
    __half* whcakv = wh + 5 * EE;     // [2E, E]
    __half* whcao  = wh + 7 * EE;     // [E, E]
    __half* whw1   = wh + 8 * EE;     // [FF, E]
    __half* whw2   = wh + 8 * EE + EFF; // [E, FF]

    const int RT = 256;
    const int nEE  = EE / 4, nEFF = EFF / 4, nME = M_ * E_ / 4;
    dim3 gQKV(3 * E_ / GBN, M_ / GBM);   // (12, 64)
    dim3 gKV (2 * E_ / GBN, M_ / GBM);   // (8, 64)
    dim3 g1  (E_ / GBN, M_ / GBM);       // (4, 64)
    dim3 gF1 (FF_ / GBN, M_ / GBM);      // (16, 64)
    dim3 ga  (L_ / 128, B_ * H_);        // (16, 64)

    // ---- converts (self-attn) ----
    cvt_h_kernel<<<(nME + RT - 1) / RT, RT>>>(tgt,  tgh,           nME);  // #0
    cvt_h_kernel<<<(nEE + RT - 1) / RT, RT>>>(saWq, whqkv,         nEE);  // #1
    cvt_h_kernel<<<(nEE + RT - 1) / RT, RT>>>(saWk, whqkv + EE,    nEE);  // #2
    cvt_h_kernel<<<(nEE + RT - 1) / RT, RT>>>(saWv, whqkv + 2*EE,  nEE);  // #3
    cvt_h_kernel<<<(nEE + RT - 1) / RT, RT>>>(saWo, whsao,         nEE);  // #4

    // ---- self attention ----
    gemm_f16<false, 3, false><<<gQKV, 256, GEMM_SMEM>>>(              // #5 (ncu)
        tgh, whqkv, sabq, sabk, sabv, qkv, 3 * E_, E_);
    flash_mma_kernel<true><<<ga, 256, FL_SMEM>>>(
        qkv, 3 * E_, qkv + E_, qkv + 2 * E_, 3 * E_, ao, L_);
    gemm_f16<false, 1, false><<<g1, 256, GEMM_SMEM>>>(
        ao, whsao, sabo, sabo, sabo, t, E_, E_);
    add_ln_kernel<true><<<M_, 256>>>(tgt, t, ln1g, ln1b, x1, x1h);

    // ---- converts (cross-attn, FFN) ----
    cvt_h_kernel<<<(nME + RT - 1) / RT, RT>>>(memi, meh,          nME);
    cvt_h_kernel<<<(nEE + RT - 1) / RT, RT>>>(caWq, whcaq,        nEE);
    cvt_h_kernel<<<(nEE + RT - 1) / RT, RT>>>(caWk, whcakv,       nEE);
    cvt_h_kernel<<<(nEE + RT - 1) / RT, RT>>>(caWv, whcakv + EE,  nEE);
    cvt_h_kernel<<<(nEE + RT - 1) / RT, RT>>>(caWo, whcao,        nEE);
    cvt_h_kernel<<<(nEFF + RT - 1) / RT, RT>>>(W1, whw1, nEFF);
    cvt_h_kernel<<<(nEFF + RT - 1) / RT, RT>>>(W2, whw2, nEFF);

    // ---- cross attention ----
    gemm_f16<false, 1, false><<<g1, 256, GEMM_SMEM>>>(
        x1h, whcaq, cabq, cabq, cabq, q, E_, E_);
    gemm_f16<false, 3, false><<<gKV, 256, GEMM_SMEM>>>(
        meh, whcakv, cabk, cabv, cabv, kv, 2 * E_, E_);
    flash_mma_kernel<false><<<ga, 256, FL_SMEM>>>(
        q, E_, kv, kv + E_, 2 * E_, ao, S_);
    gemm_f16<false, 1, false><<<g1, 256, GEMM_SMEM>>>(
        ao, whcao, cabo, cabo, cabo, t, E_, E_);
    add_ln_kernel<true><<<M_, 256>>>(x1, t, ln2g, ln2b, x2, x2h);

    // ---- FFN ----
    gemm_f16<true, 1, true><<<gF1, 256, GEMM_SMEM>>>(
        x2h, whw1, b1, b1, b1, hh, FF_, E_);
    gemm_f16<false, 1, false><<<g1, 256, GEMM_SMEM>>>(
        hh, whw2, b2, b2, b2, t, E_, FF_);
    add_ln_kernel<false><<<M_, 256>>>(x2, t, ln3g, ln3b, (float*)d_out, nullptr);
}

// round 10
// speedup vs baseline: 2.1214x; 1.2012x over previous
#include <cuda_runtime.h>
#include <cuda_fp16.h>
#include <cstdint>

#define L_  2048
#define S_  2048
#define B_  4
#define E_  1024
#define H_  16
#define HD_ 64
#define FF_ 4096
#define M_  (L_*B_)
#define EPS_ 1e-5f

// ---------------- device scratch ------------------------------------------
__device__ __half g_qkv[M_*3*E_];
__device__ __half g_q  [M_*E_];
__device__ __half g_kv [M_*2*E_];
__device__ __half g_ao [M_*E_];
__device__ float  g_t  [M_*E_];
__device__ float  g_x1 [M_*E_];
__device__ float  g_x2 [M_*E_];
__device__ __half g_x1h[M_*E_];
__device__ __half g_x2h[M_*E_];
__device__ __half g_tgh[M_*E_];
__device__ __half g_meh[M_*E_];
__device__ __half g_hh [M_*FF_];
__device__ __half g_wh [8*E_*E_ + 2*E_*FF_];

// ---------------- PTX helpers ---------------------------------------------
__device__ __forceinline__ uint32_t h2_bits(__half2 h) {
    uint32_t u;
    asm("mov.b32 %0, %1;" : "=r"(u) : "r"(*(uint32_t*)&h));
    return u;
}
__device__ __forceinline__ void cpa16(void* smem, const void* gmem) {
    uint32_t s = (uint32_t)__cvta_generic_to_shared(smem);
    asm volatile("cp.async.cg.shared.global [%0], [%1], 16;" :: "r"(s), "l"(gmem));
}
__device__ __forceinline__ void mma_f16(float* d, const uint32_t* a, const uint32_t* b) {
    asm volatile(
        "mma.sync.aligned.m16n8k16.row.col.f32.f16.f16.f32 "
        "{%0,%1,%2,%3}, {%4,%5,%6,%7}, {%8,%9}, {%0,%1,%2,%3};"
        : "+f"(d[0]), "+f"(d[1]), "+f"(d[2]), "+f"(d[3])
        : "r"(a[0]), "r"(a[1]), "r"(a[2]), "r"(a[3]), "r"(b[0]), "r"(b[1]));
}

// ---------------- f32 -> f16 converts --------------------------------------
__global__ void cvt_h_kernel(const float* __restrict__ in,
                             __half* __restrict__ out, int n4) {
    int i = blockIdx.x * blockDim.x + threadIdx.x;
    if (i < n4) {
        float4 v = *(const float4*)&in[i * 4];
        __half2 h0 = __floats2half2_rn(v.x, v.y);
        __half2 h1 = __floats2half2_rn(v.z, v.w);
        *(uint2*)&out[i * 4] = make_uint2(h2_bits(h0), h2_bits(h1));
    }
}
// all 10 weights -> g_wh in one launch; 16 EE-sized chunks (grid.y)
__global__ void cvt_weights_kernel(
    const float* w0, const float* w1, const float* w2, const float* w3,
    const float* w4, const float* w5, const float* w6, const float* w7,
    const float* wf1, const float* wf2, __half* __restrict__ dst) {
    const int EE = E_ * E_;
    int c = blockIdx.y;
    const float* src;
    if (c < 8) {
        const float* tbl[8] = {w0, w1, w2, w3, w4, w5, w6, w7};
        src = tbl[c];
    } else if (c < 12) {
        src = wf1 + (size_t)(c - 8) * EE;
    } else {
        src = wf2 + (size_t)(c - 12) * EE;
    }
    __half* d = dst + (size_t)c * EE;
    int i = blockIdx.x * blockDim.x + threadIdx.x;
    float4 v = *(const float4*)&src[i * 4];
    __half2 h0 = __floats2half2_rn(v.x, v.y);
    __half2 h1 = __floats2half2_rn(v.z, v.w);
    *(uint2*)&d[i * 4] = make_uint2(h2_bits(h0), h2_bits(h1));
}

// ---------------- FP16 tensor-core GEMM ------------------------------------
#define GBM 128
#define GBN 256
#define GBK 32
#define HPAD 40
#define ASTGH (GBM*HPAD)
#define BSTGH (GBN*HPAD)
#define NSTG 3
#define GEMM_SMEM (NSTG*(ASTGH+BSTGH)*2)   /* 92160 bytes */

template <bool RELU, int NBSEL, bool HOUT>
__global__ __launch_bounds__(256, 1)
void gemm_f16(const __half* __restrict__ A, const __half* __restrict__ W,
              const float* __restrict__ bb0, const float* __restrict__ bb1,
              const float* __restrict__ bb2, void* __restrict__ Cv,
              int N, int K) {
    extern __shared__ __half sm[];
    const int tid  = threadIdx.x;
    const int lane = tid & 31, warp = tid >> 5;
    const int gid  = lane >> 2, tig = lane & 3;
    const int wm   = (warp & 1) * 64;
    const int wn   = (warp >> 1) * 64;
    const int m0   = blockIdx.y * GBM, n0 = blockIdx.x * GBN;

    float acc[4][8][4];
    #pragma unroll
    for (int mt = 0; mt < 4; mt++)
        #pragma unroll
        for (int nt = 0; nt < 8; nt++)
            #pragma unroll
            for (int i = 0; i < 4; i++) acc[mt][nt][i] = 0.0f;

    const int nC = K / GBK;

    #define LOAD_STAGE(s, k0)                                                      \
        do {                                                                       \
            __half* As_ = sm + (s) * ASTGH;                                        \
            __half* Bs_ = sm + NSTG * ASTGH + (s) * BSTGH;                         \
            _Pragma("unroll")                                                      \
            for (int i = 0; i < 2; i++) {                                          \
                int u = tid + i * 256, row = u >> 2, ch = (u & 3) * 8;             \
                cpa16(&As_[row * HPAD + ch],                                       \
                      A + (size_t)(m0 + row) * K + (k0) + ch);                     \
            }                                                                      \
            _Pragma("unroll")                                                      \
            for (int i = 0; i < 4; i++) {                                          \
                int u = tid + i * 256, row = u >> 2, ch = (u & 3) * 8;             \
                cpa16(&Bs_[row * HPAD + ch],                                       \
                      W + (size_t)(n0 + row) * K + (k0) + ch);                     \
            }                                                                      \
            asm volatile("cp.async.commit_group;");                                \
        } while (0)

    LOAD_STAGE(0, 0);
    LOAD_STAGE(1, GBK);

    for (int kt = 0; kt < nC; kt++) {
        asm volatile("cp.async.wait_group 1;");
        __syncthreads();
        const int st = kt % 3;
        if (kt + 2 < nC) LOAD_STAGE((kt + 2) % 3, (kt + 2) * GBK);

        const __half* As_ = sm + st * ASTGH;
        const __half* Bs_ = sm + NSTG * ASTGH + st * BSTGH;
        #pragma unroll
        for (int kk = 0; kk < GBK; kk += 16) {
            uint32_t af[4][4], bf[8][2];
            #pragma unroll
            for (int mt = 0; mt < 4; mt++) {
                int mr = wm + mt * 16 + gid;
                af[mt][0] = *(const uint32_t*)&As_[mr * HPAD + kk + 2 * tig];
                af[mt][1] = *(const uint32_t*)&As_[(mr + 8) * HPAD + kk + 2 * tig];
                af[mt][2] = *(const uint32_t*)&As_[mr * HPAD + kk + 2 * tig + 8];
                af[mt][3] = *(const uint32_t*)&As_[(mr + 8) * HPAD + kk + 2 * tig + 8];
            }
            #pragma unroll
            for (int nt = 0; nt < 8; nt++) {
                int nc = wn + nt * 8 + gid;
                bf[nt][0] = *(const uint32_t*)&Bs_[nc * HPAD + kk + 2 * tig];
                bf[nt][1] = *(const uint32_t*)&Bs_[nc * HPAD + kk + 2 * tig + 8];
            }
            #pragma unroll
            for (int mt = 0; mt < 4; mt++)
                #pragma unroll
                for (int nt = 0; nt < 8; nt++)
                    mma_f16(acc[mt][nt], af[mt], bf[nt]);
        }
        __syncthreads();
    }
    #undef LOAD_STAGE

    #pragma unroll
    for (int mt = 0; mt < 4; mt++) {
        int r0 = m0 + wm + mt * 16 + gid;
        #pragma unroll
        for (int nt = 0; nt < 8; nt++) {
            int col = n0 + wn + nt * 8 + tig * 2;
            const float* bp = bb0;
            int bcol = col;
            if (NBSEL == 3) {
                int sel = col >> 10;
                bp = (sel == 0) ? bb0 : (sel == 1 ? bb1 : bb2);
                bcol = col & 1023;
            }
            float bv0 = bp[bcol], bv1 = bp[bcol + 1];
            float v0 = acc[mt][nt][0] + bv0, v1 = acc[mt][nt][1] + bv1;
            float v2 = acc[mt][nt][2] + bv0, v3 = acc[mt][nt][3] + bv1;
            if (RELU) {
                v0 = fmaxf(v0, 0.f); v1 = fmaxf(v1, 0.f);
                v2 = fmaxf(v2, 0.f); v3 = fmaxf(v3, 0.f);
            }
            if (HOUT) {
                __half* C = (__half*)Cv;
                *(uint32_t*)&C[(size_t)r0 * N + col]       = h2_bits(__floats2half2_rn(v0, v1));
                *(uint32_t*)&C[(size_t)(r0 + 8) * N + col] = h2_bits(__floats2half2_rn(v2, v3));
            } else {
                float* C = (float*)Cv;
                *(float2*)&C[(size_t)r0 * N + col]       = make_float2(v0, v1);
                *(float2*)&C[(size_t)(r0 + 8) * N + col] = make_float2(v2, v3);
            }
        }
    }
}

// ---------------- flash attention (FP16 mma, HD=64) ------------------------
#define KROW 72
#define FTILE (64*KROW)
#define FL_SMEM (4*FTILE*2)                 /* 36864 bytes */

template <bool CAUSAL>
__global__ __launch_bounds__(256)
void flash_f16_kernel(const __half* __restrict__ Q, int qrs,
                      const __half* __restrict__ Kg, const __half* __restrict__ Vg,
                      int krs, __half* __restrict__ O, int Slen) {
    extern __shared__ __half hsm[];
    __half* KsB = hsm;              // [2][FTILE]
    __half* VsB = hsm + 2 * FTILE;  // [2][FTILE], V transposed [d][s] + swizzle

    const int tid = threadIdx.x, warp = tid >> 5, lane = tid & 31;
    const int gid = lane >> 2, tig = lane & 3;
    const int bh = blockIdx.y, b = bh >> 4, h = bh & 15;
    const int l0 = blockIdx.x * 128;
    const int col = h * HD_;
    const int rw = l0 + warp * 16;

    const int sp = tid >> 3, dc = tid & 7;   // V-fill: s-pair, d-chunk

    uint32_t qf[4][4];
    {
        const __half2 sc = __float2half2_rn(0.125f);
        const __half* q0 = &Q[((size_t)(rw + gid) * B_ + b) * qrs + col];
        const __half* q1 = &Q[((size_t)(rw + gid + 8) * B_ + b) * qrs + col];
        #pragma unroll
        for (int kk = 0; kk < 4; kk++) {
            qf[kk][0] = h2_bits(__hmul2(*(const __half2*)&q0[kk * 16 + 2 * tig], sc));
            qf[kk][1] = h2_bits(__hmul2(*(const __half2*)&q1[kk * 16 + 2 * tig], sc));
            qf[kk][2] = h2_bits(__hmul2(*(const __half2*)&q0[kk * 16 + 2 * tig + 8], sc));
            qf[kk][3] = h2_bits(__hmul2(*(const __half2*)&q1[kk * 16 + 2 * tig + 8], sc));
        }
    }

    float of[8][4];
    #pragma unroll
    for (int nt = 0; nt < 8; nt++)
        of[nt][0] = of[nt][1] = of[nt][2] = of[nt][3] = 0.f;
    float m0 = -1e30f, m1 = -1e30f, la0 = 0.f, la1 = 0.f;

    const int T = CAUSAL ? (l0 / 64 + 2) : (Slen / 64);

    // prologue: tile 0 (K async, V transposed fill)
    {
        #pragma unroll
        for (int i = 0; i < 2; i++) {
            int u = tid + i * 256;
            int r = u >> 3, c8 = (u & 7) * 8;
            cpa16(&KsB[r * KROW + c8], &Kg[((size_t)r * B_ + b) * krs + col + c8]);
        }
        asm volatile("cp.async.commit_group;");
        const __half* vp0 = &Vg[((size_t)(2 * sp) * B_ + b) * krs + col + dc * 8];
        uint4 r0 = *(const uint4*)vp0;
        uint4 r1 = *(const uint4*)(vp0 + (size_t)B_ * krs);
        const __half* ha = (const __half*)&r0;
        const __half* hb = (const __half*)&r1;
        #pragma unroll
        for (int j = 0; j < 8; j++) {
            int d = dc * 8 + j;
            *(uint32_t*)&VsB[d * KROW + 2 * (sp ^ (dc << 2))] =
                h2_bits(__halves2half2(ha[j], hb[j]));
        }
    }

    for (int t = 0; t < T; t++) {
        const int bf = t & 1;
        uint4 vr0, vr1;
        if (t + 1 < T) {
            const int s1 = (t + 1) * 64, b2 = bf ^ 1;
            __half* Kn = KsB + b2 * FTILE;
            #pragma unroll
            for (int i = 0; i < 2; i++) {
                int u = tid + i * 256;
                int r = u >> 3, c8 = (u & 7) * 8;
                cpa16(&Kn[r * KROW + c8], &Kg[((size_t)(s1 + r) * B_ + b) * krs + col + c8]);
            }
            asm volatile("cp.async.commit_group;");
            const __half* vp0 = &Vg[((size_t)(s1 + 2 * sp) * B_ + b) * krs + col + dc * 8];
            vr0 = *(const uint4*)vp0;
            vr1 = *(const uint4*)(vp0 + (size_t)B_ * krs);
            asm volatile("cp.async.wait_group 1;");
        } else {
            asm volatile("cp.async.wait_group 0;");
        }
        __syncthreads();

        const int s0 = t * 64;
        if (!CAUSAL || s0 <= rw) {
            const __half* Ksb = KsB + bf * FTILE;
            const __half* Vsb = VsB + bf * FTILE;
            float sf[8][4];
            #pragma unroll
            for (int nt = 0; nt < 8; nt++)
                sf[nt][0] = sf[nt][1] = sf[nt][2] = sf[nt][3] = 0.f;
            #pragma unroll
            for (int kk = 0; kk < 4; kk++) {
                #pragma unroll
                for (int nt = 0; nt < 8; nt++) {
                    uint32_t bb[2];
                    const __half* kr = &Ksb[(nt * 8 + gid) * KROW + kk * 16 + 2 * tig];
                    bb[0] = *(const uint32_t*)kr;
                    bb[1] = *(const uint32_t*)(kr + 8);
                    mma_f16(sf[nt], qf[kk], bb);
                }
            }
            if (CAUSAL && s0 + 63 > rw) {
                int r0 = rw + gid, r1 = r0 + 8;
                #pragma unroll
                for (int nt = 0; nt < 8; nt++) {
                    int c = s0 + nt * 8 + 2 * tig;
                    if (c     > r0) sf[nt][0] = -1e30f;
                    if (c + 1 > r0) sf[nt][1] = -1e30f;
                    if (c     > r1) sf[nt][2] = -1e30f;
                    if (c + 1 > r1) sf[nt][3] = -1e30f;
                }
            }
            float mx0 = -1e30f, mx1 = -1e30f;
            #pragma unroll
            for (int nt = 0; nt < 8; nt++) {
                mx0 = fmaxf(mx0, fmaxf(sf[nt][0], sf[nt][1]));
                mx1 = fmaxf(mx1, fmaxf(sf[nt][2], sf[nt][3]));
            }
            mx0 = fmaxf(mx0, __shfl_xor_sync(0xffffffffu, mx0, 1));
            mx0 = fmaxf(mx0, __shfl_xor_sync(0xffffffffu, mx0, 2));
            mx1 = fmaxf(mx1, __shfl_xor_sync(0xffffffffu, mx1, 1));
            mx1 = fmaxf(mx1, __shfl_xor_sync(0xffffffffu, mx1, 2));
            float mn0 = fmaxf(m0, mx0), mn1 = fmaxf(m1, mx1);
            float f0 = __expf(m0 - mn0), f1 = __expf(m1 - mn1);
            m0 = mn0;  m1 = mn1;
            float ss0 = 0.f, ss1 = 0.f;
            #pragma unroll
            for (int nt = 0; nt < 8; nt++) {
                sf[nt][0] = __expf(sf[nt][0] - m0);  ss0 += sf[nt][0];
                sf[nt][1] = __expf(sf[nt][1] - m0);  ss0 += sf[nt][1];
                sf[nt][2] = __expf(sf[nt][2] - m1);  ss1 += sf[nt][2];
                sf[nt][3] = __expf(sf[nt][3] - m1);  ss1 += sf[nt][3];
            }
            ss0 += __shfl_xor_sync(0xffffffffu, ss0, 1);
            ss0 += __shfl_xor_sync(0xffffffffu, ss0, 2);
            ss1 += __shfl_xor_sync(0xffffffffu, ss1, 1);
            ss1 += __shfl_xor_sync(0xffffffffu, ss1, 2);
            la0 = la0 * f0 + ss0;
            la1 = la1 * f1 + ss1;
            #pragma unroll
            for (int nt = 0; nt < 8; nt++) {
                of[nt][0] *= f0;  of[nt][1] *= f0;
                of[nt][2] *= f1;  of[nt][3] *= f1;
            }
            // P C-fragment -> fp16 A-fragment: identity per-thread mapping
            #pragma unroll
            for (int kk = 0; kk < 4; kk++) {
                uint32_t a[4];
                a[0] = h2_bits(__floats2half2_rn(sf[2*kk][0],   sf[2*kk][1]));
                a[1] = h2_bits(__floats2half2_rn(sf[2*kk][2],   sf[2*kk][3]));
                a[2] = h2_bits(__floats2half2_rn(sf[2*kk+1][0], sf[2*kk+1][1]));
                a[3] = h2_bits(__floats2half2_rn(sf[2*kk+1][2], sf[2*kk+1][3]));
                #pragma unroll
                for (int nt = 0; nt < 8; nt++) {
                    int d = nt * 8 + gid;
                    uint32_t bb[2];
                    bb[0] = *(const uint32_t*)&Vsb[d * KROW + 2 * ((8*kk + tig)     ^ (nt << 2))];
                    bb[1] = *(const uint32_t*)&Vsb[d * KROW + 2 * ((8*kk + tig + 4) ^ (nt << 2))];
                    mma_f16(of[nt], a, bb);
                }
            }
        }
        if (t + 1 < T) {
            __half* Vn = VsB + ((bf ^ 1)) * FTILE;
            const __half* ha = (const __half*)&vr0;
            const __half* hb = (const __half*)&vr1;
            #pragma unroll
            for (int j = 0; j < 8; j++) {
                int d = dc * 8 + j;
                *(uint32_t*)&Vn[d * KROW + 2 * (sp ^ (dc << 2))] =
                    h2_bits(__halves2half2(ha[j], hb[j]));
            }
        }
        __syncthreads();
    }

    const float inv0 = 1.f / la0, inv1 = 1.f / la1;
    const int r0 = rw + gid, r1 = r0 + 8;
    #pragma unroll
    for (int nt = 0; nt < 8; nt++) {
        int c = col + nt * 8 + 2 * tig;
        *(uint32_t*)&O[((size_t)r0 * B_ + b) * E_ + c] =
            h2_bits(__floats2half2_rn(of[nt][0] * inv0, of[nt][1] * inv0));
        *(uint32_t*)&O[((size_t)r1 * B_ + b) * E_ + c] =
            h2_bits(__floats2half2_rn(of[nt][2] * inv1, of[nt][3] * inv1));
    }
}

// ---------------- fused residual + LayerNorm (+opt fp16 twin) --------------
template <bool WH>
__global__ __launch_bounds__(256)
void add_ln_kernel(const float* __restrict__ A, const float* __restrict__ Bb,
                   const float* __restrict__ g, const float* __restrict__ be,
                   float* __restrict__ out, __half* __restrict__ outH) {
    __shared__ float rbuf[8];
    __shared__ float stat;
    int row = blockIdx.x, tid = threadIdx.x, lane = tid & 31, warp = tid >> 5;
    size_t base = (size_t)row * E_ + tid * 4;

    float4 a = *(const float4*)&A[base];
    float4 b = *(const float4*)&Bb[base];
    float4 x = make_float4(a.x + b.x, a.y + b.y, a.z + b.z, a.w + b.w);

    float s = x.x + x.y + x.z + x.w;
    #pragma unroll
    for (int off = 16; off > 0; off >>= 1) s += __shfl_xor_sync(0xffffffffu, s, off);
    if (lane == 0) rbuf[warp] = s;
    __syncthreads();
    if (tid == 0) {
        float t = 0.f;
        #pragma unroll
        for (int i = 0; i < 8; i++) t += rbuf[i];
        stat = t * (1.0f / E_);
    }
    __syncthreads();
    float mu = stat;

    float4 dx = make_float4(x.x - mu, x.y - mu, x.z - mu, x.w - mu);
    float sq = dx.x * dx.x + dx.y * dx.y + dx.z * dx.z + dx.w * dx.w;
    #pragma unroll
    for (int off = 16; off > 0; off >>= 1) sq += __shfl_xor_sync(0xffffffffu, sq, off);
    if (lane == 0) rbuf[warp] = sq;
    __syncthreads();
    if (tid == 0) {
        float t = 0.f;
        #pragma unroll
        for (int i = 0; i < 8; i++) t += rbuf[i];
        stat = rsqrtf(t * (1.0f / E_) + EPS_);
    }
    __syncthreads();
    float rs = stat;

    float4 gv = *(const float4*)&g[tid * 4];
    float4 bv = *(const float4*)&be[tid * 4];
    float4 y = make_float4(dx.x * rs * gv.x + bv.x, dx.y * rs * gv.y + bv.y,
                           dx.z * rs * gv.z + bv.z, dx.w * rs * gv.w + bv.w);
    *(float4*)&out[base] = y;
    if (WH) {
        __half2 h0 = __floats2half2_rn(y.x, y.y);
        __half2 h1 = __floats2half2_rn(y.z, y.w);
        *(uint2*)&outH[base] = make_uint2(h2_bits(h0), h2_bits(h1));
    }
}

// ---------------- launcher ------------------------------------------------
extern "C" void kernel_launch(void* const* d_in, const int* in_sizes, int n_in,
                              void* d_out, int out_size) {
    (void)in_sizes; (void)n_in; (void)out_size;
    const float* tgt  = (const float*)d_in[0];
    const float* memi = (const float*)d_in[1];
    // d_in[2] = tgt_mask: strictly causal by construction; causal predicate used instead.
    const float* saWq = (const float*)d_in[3];  const float* sabq = (const float*)d_in[4];
    const float* saWk = (const float*)d_in[5];  const float* sabk = (const float*)d_in[6];
    const float* saWv = (const float*)d_in[7];  const float* sabv = (const float*)d_in[8];
    const float* saWo = (const float*)d_in[9];  const float* sabo = (const float*)d_in[10];
    const float* caWq = (const float*)d_in[11]; const float* cabq = (const float*)d_in[12];
    const float* caWk = (const float*)d_in[13]; const float* cabk = (const float*)d_in[14];
    const float* caWv = (const float*)d_in[15]; const float* cabv = (const float*)d_in[16];
    const float* caWo = (const float*)d_in[17]; const float* cabo = (const float*)d_in[18];
    const float* W1   = (const float*)d_in[19]; const float* b1   = (const float*)d_in[20];
    const float* W2   = (const float*)d_in[21]; const float* b2   = (const float*)d_in[22];
    const float* ln1g = (const float*)d_in[23]; const float* ln1b = (const float*)d_in[24];
    const float* ln2g = (const float*)d_in[25]; const float* ln2b = (const float*)d_in[26];
    const float* ln3g = (const float*)d_in[27]; const float* ln3b = (const float*)d_in[28];

    float  *t, *x1, *x2;
    __half *qkv, *q, *kv, *ao, *x1h, *x2h, *tgh, *meh, *hh, *wh;
    cudaGetSymbolAddress((void**)&qkv, g_qkv);
    cudaGetSymbolAddress((void**)&q,   g_q);
    cudaGetSymbolAddress((void**)&kv,  g_kv);
    cudaGetSymbolAddress((void**)&ao,  g_ao);
    cudaGetSymbolAddress((void**)&t,   g_t);
    cudaGetSymbolAddress((void**)&x1,  g_x1);
    cudaGetSymbolAddress((void**)&x2,  g_x2);
    cudaGetSymbolAddress((void**)&x1h, g_x1h);
    cudaGetSymbolAddress((void**)&x2h, g_x2h);
    cudaGetSymbolAddress((void**)&tgh, g_tgh);
    cudaGetSymbolAddress((void**)&meh, g_meh);
    cudaGetSymbolAddress((void**)&hh,  g_hh);
    cudaGetSymbolAddress((void**)&wh,  g_wh);

    cudaFuncSetAttribute(flash_f16_kernel<true>,
                         cudaFuncAttributeMaxDynamicSharedMemorySize, FL_SMEM);
    cudaFuncSetAttribute(flash_f16_kernel<false>,
                         cudaFuncAttributeMaxDynamicSharedMemorySize, FL_SMEM);
    cudaFuncSetAttribute(gemm_f16<false, 3, true>,
                         cudaFuncAttributeMaxDynamicSharedMemorySize, GEMM_SMEM);
    cudaFuncSetAttribute(gemm_f16<false, 1, true>,
                         cudaFuncAttributeMaxDynamicSharedMemorySize, GEMM_SMEM);
    cudaFuncSetAttribute(gemm_f16<false, 1, false>,
                         cudaFuncAttributeMaxDynamicSharedMemorySize, GEMM_SMEM);
    cudaFuncSetAttribute(gemm_f16<true, 1, true>,
                         cudaFuncAttributeMaxDynamicSharedMemorySize, GEMM_SMEM);

    const int EE = E_ * E_, EFF = E_ * FF_;
    __half* whqkv  = wh;
    __half* whsao  = wh + 3 * EE;
    __half* whcaq  = wh + 4 * EE;
    __half* whcakv = wh + 5 * EE;
    __half* whcao  = wh + 7 * EE;
    __half* whw1   = wh + 8 * EE;
    __half* whw2   = wh + 8 * EE + EFF;

    const int RT = 256;
    const int nEE = EE / 4, nME = M_ * E_ / 4;
    dim3 gQKV(3 * E_ / GBN, M_ / GBM);
    dim3 gKV (2 * E_ / GBN, M_ / GBM);
    dim3 g1  (E_ / GBN, M_ / GBM);
    dim3 gF1 (FF_ / GBN, M_ / GBM);
    dim3 ga  (L_ / 128, B_ * H_);

    // ---- converts ----
    cvt_h_kernel<<<(nME + RT - 1) / RT, RT>>>(tgt,  tgh, nME);
    cvt_h_kernel<<<(nME + RT - 1) / RT, RT>>>(memi, meh, nME);
    cvt_weights_kernel<<<dim3(nEE / RT, 16), RT>>>(
        saWq, saWk, saWv, saWo, caWq, caWk, caWv, caWo, W1, W2, wh);

    // ---- self attention ----
    gemm_f16<false, 3, true><<<gQKV, 256, GEMM_SMEM>>>(
        tgh, whqkv, sabq, sabk, sabv, qkv, 3 * E_, E_);
    flash_f16_kernel<true><<<ga, 256, FL_SMEM>>>(
        qkv, 3 * E_, qkv + E_, qkv + 2 * E_, 3 * E_, ao, L_);
    gemm_f16<false, 1, false><<<g1, 256, GEMM_SMEM>>>(
        ao, whsao, sabo, sabo, sabo, t, E_, E_);
    add_ln_kernel<true><<<M_, 256>>>(tgt, t, ln1g, ln1b, x1, x1h);

    // ---- cross attention ----
    gemm_f16<false, 1, true><<<g1, 256, GEMM_SMEM>>>(
        x1h, whcaq, cabq, cabq, cabq, q, E_, E_);
    gemm_f16<false, 3, true><<<gKV, 256, GEMM_SMEM>>>(
        meh, whcakv, cabk, cabv, cabv, kv, 2 * E_, E_);
    flash_f16_kernel<false><<<ga, 256, FL_SMEM>>>(
        q, E_, kv, kv + E_, 2 * E_, ao, S_);
    gemm_f16<false, 1, false><<<g1, 256, GEMM_SMEM>>>(
        ao, whcao, cabo, cabo, cabo, t, E_, E_);
    add_ln_kernel<true><<<M_, 256>>>(x1, t, ln2g, ln2b, x2, x2h);

    // ---- FFN ----
    gemm_f16<true, 1, true><<<gF1, 256, GEMM_SMEM>>>(
        x2h, whw1, b1, b1, b1, hh, FF_, E_);
    gemm_f16<false, 1, false><<<g1, 256, GEMM_SMEM>>>(
        hh, whw2, b2, b2, b2, t, E_, FF_);
    add_ln_kernel<false><<<M_, 256>>>(x2, t, ln3g, ln3b, (float*)d_out, nullptr);
}